// round 2
// baseline (speedup 1.0000x reference)
#include <cuda_runtime.h>

// ---------------------------------------------------------------------------
// EGNN-ish model:
//   edge kernel: gather features -> phi_e (3 GEMMs + LN + softplus) and
//                phi_v (1 GEMM + LN + softplus + dot) -> atomic scatter
//   node kernel: build hin -> phi_h (GEMM + LN + softplus + GEMM) + residual
// fp32 baseline, register-blocked smem GEMMs (128x128 tiles, 8x8/thread).
// ---------------------------------------------------------------------------

namespace {
constexpr int NNODES = 20000;
constexpr int NEDGES = 640000;
constexpr int C      = 64;
constexpr int H      = 128;
constexpr int F      = 133;   // 2C + 5
constexpr int KF     = 136;   // padded K for edge MLP input
constexpr int KH     = 193;   // C + H + 1
constexpr int KHP    = 200;   // padded
constexpr int ETILE  = 128;
}

__device__ float g_mh[NNODES * H];
__device__ float g_mv[NNODES * 2];
__device__ float g_cnt[NNODES];

struct EdgeParams {
  const float *x, *pos, *vel;
  const float *We1, *be1, *ge1, *bte1, *We2, *be2, *We3, *be3;
  const float *Wv1, *bv1, *gv1, *btv1, *Wv2, *bv2;
  const int   *ei;
};
struct NodeParams {
  const float *x;
  const float *Wh1, *bh1, *gh1, *bth1, *Wh2, *bh2;
  float       *out;
};

__global__ void zero_kernel() {
  int i = blockIdx.x * 256 + threadIdx.x;
  if (i < NNODES * H) g_mh[i] = 0.f;
  if (i < NNODES * 2) g_mv[i] = 0.f;
  if (i < NNODES)     g_cnt[i] = 0.f;
}

__device__ __forceinline__ float softplus_f(float v) {
  return fmaxf(v, 0.f) + log1pf(__expf(-fabsf(v)));
}

extern __shared__ float smem_dyn[];

// C = A[128 x K] * W[K x 128], A in smem (row stride STRIDE), W streamed from
// global through an smem chunk buffer with register prefetch.
template <int STRIDE, int KACT, int NCHUNK>
__device__ __forceinline__ void gemm_tile(const float* __restrict__ W,
                                          const float* sA_, float* sB_,
                                          float acc[8][8], int tx, int ty,
                                          int tid) {
  int wrow = tid >> 5, wc4 = tid & 31;
  float4 v;
  {
    int k = wrow;
    v = (k < KACT) ? reinterpret_cast<const float4*>(W)[k * 32 + wc4]
                   : make_float4(0.f, 0.f, 0.f, 0.f);
  }
#pragma unroll 1
  for (int ch = 0; ch < NCHUNK; ++ch) {
    reinterpret_cast<float4*>(sB_)[tid] = v;
    __syncthreads();
    if (ch + 1 < NCHUNK) {
      int k = (ch + 1) * 8 + wrow;
      v = (k < KACT) ? reinterpret_cast<const float4*>(W)[k * 32 + wc4]
                     : make_float4(0.f, 0.f, 0.f, 0.f);
    }
    int k0 = ch * 8;
#pragma unroll
    for (int kk = 0; kk < 8; ++kk) {
      float a[8];
#pragma unroll
      for (int r = 0; r < 8; ++r) a[r] = sA_[(ty * 8 + r) * STRIDE + k0 + kk];
      const float4* bp = reinterpret_cast<const float4*>(sB_ + kk * 128 + tx * 8);
      float4 b0 = bp[0], b1 = bp[1];
      float b[8] = {b0.x, b0.y, b0.z, b0.w, b1.x, b1.y, b1.z, b1.w};
#pragma unroll
      for (int r = 0; r < 8; ++r)
#pragma unroll
        for (int c = 0; c < 8; ++c) acc[r][c] = fmaf(a[r], b[c], acc[r][c]);
    }
    __syncthreads();
  }
}

__global__ void __launch_bounds__(256, 1) edge_kernel(EdgeParams p) {
  float* sA   = smem_dyn;            // 128 * KF
  float* sH   = sA + ETILE * KF;     // 128 * 128
  float* sB   = sH + ETILE * H;      // 8 * 128
  float* sRel = sB + 8 * H;          // 128 * 2
  int*   sDst = (int*)(sRel + 2 * ETILE);
  int*   sSrc = sDst + ETILE;

  int tid = threadIdx.x;
  int tx = tid & 15, ty = tid >> 4;
  int e0 = blockIdx.x * ETILE;

  if (tid < ETILE) {
    int e = e0 + tid;
    int s = p.ei[e], d = p.ei[NEDGES + e];
    sSrc[tid] = s;
    sDst[tid] = d;
    float rpx = p.pos[2 * s] - p.pos[2 * d];
    float rpy = p.pos[2 * s + 1] - p.pos[2 * d + 1];
    float rvx = p.vel[2 * s] - p.vel[2 * d];
    float rvy = p.vel[2 * s + 1] - p.vel[2 * d + 1];
    float dist = rpx * rpx + rpy * rpy;
    float dvr  = rvx * rpx + rvy * rpy;
    float r2   = fminf(1.f / (dist + 0.05f), 20.f);
    float r6   = fminf(r2 * r2 * r2, 400.f);
    float r12  = fminf(r6 * r6, 160000.f);
    float* row = &sA[tid * KF];
    row[128] = dist; row[129] = dvr; row[130] = r2; row[131] = r6;
    row[132] = r12;  row[133] = 0.f; row[134] = 0.f; row[135] = 0.f;
    sRel[2 * tid] = rpx;
    sRel[2 * tid + 1] = rpy;
  }
  __syncthreads();
#pragma unroll 1
  for (int i = tid; i < ETILE * 32; i += 256) {
    int e = i >> 5, q = i & 31;
    int node = (q < 16) ? sDst[e] : sSrc[e];
    int c4 = q & 15;
    float4 vv = reinterpret_cast<const float4*>(p.x)[node * 16 + c4];
    float* dp = &sA[e * KF + ((q < 16) ? 0 : 64) + c4 * 4];
    dp[0] = vv.x; dp[1] = vv.y; dp[2] = vv.z; dp[3] = vv.w;
  }
  __syncthreads();

  float acc[8][8];

  // ------------------------- phi_v -------------------------
#pragma unroll
  for (int r = 0; r < 8; ++r)
#pragma unroll
    for (int c = 0; c < 8; ++c) acc[r][c] = 0.f;
  gemm_tile<KF, F, 17>(p.Wv1, sA, sB, acc, tx, ty, tid);
  {
    float bias[8], g[8], bt[8], w2[8];
#pragma unroll
    for (int c = 0; c < 8; ++c) {
      int col = tx * 8 + c;
      bias[c] = p.bv1[col]; g[c] = p.gv1[col];
      bt[c] = p.btv1[col];  w2[c] = p.Wv2[col];
    }
    float bv2v = p.bv2[0];
#pragma unroll
    for (int r = 0; r < 8; ++r) {
      float z[8], s = 0.f, s2 = 0.f;
#pragma unroll
      for (int c = 0; c < 8; ++c) {
        z[c] = acc[r][c] + bias[c];
        s += z[c]; s2 += z[c] * z[c];
      }
#pragma unroll
      for (int m = 1; m < 16; m <<= 1) {
        s  += __shfl_xor_sync(0xffffffffu, s, m);
        s2 += __shfl_xor_sync(0xffffffffu, s2, m);
      }
      float mu = s * (1.f / 128.f);
      float var = s2 * (1.f / 128.f) - mu * mu;
      float rinv = rsqrtf(var + 1e-5f);
      float vsum = 0.f;
#pragma unroll
      for (int c = 0; c < 8; ++c)
        vsum += softplus_f((z[c] - mu) * rinv * g[c] + bt[c]) * w2[c];
#pragma unroll
      for (int m = 1; m < 16; m <<= 1)
        vsum += __shfl_xor_sync(0xffffffffu, vsum, m);
      if (tx == 0) {
        int row = ty * 8 + r;
        int d = sDst[row];
        float vwv = vsum + bv2v;
        atomicAdd(&g_mv[2 * d],     vwv * sRel[2 * row]);
        atomicAdd(&g_mv[2 * d + 1], vwv * sRel[2 * row + 1]);
        atomicAdd(&g_cnt[d], 1.f);
      }
    }
  }

  // ---------------------- phi_e layer 1 ----------------------
#pragma unroll
  for (int r = 0; r < 8; ++r)
#pragma unroll
    for (int c = 0; c < 8; ++c) acc[r][c] = 0.f;
  gemm_tile<KF, F, 17>(p.We1, sA, sB, acc, tx, ty, tid);
  {
    float bias[8], g[8], bt[8];
#pragma unroll
    for (int c = 0; c < 8; ++c) {
      int col = tx * 8 + c;
      bias[c] = p.be1[col]; g[c] = p.ge1[col]; bt[c] = p.bte1[col];
    }
#pragma unroll
    for (int r = 0; r < 8; ++r) {
      float z[8], s = 0.f, s2 = 0.f;
#pragma unroll
      for (int c = 0; c < 8; ++c) {
        z[c] = acc[r][c] + bias[c];
        s += z[c]; s2 += z[c] * z[c];
      }
#pragma unroll
      for (int m = 1; m < 16; m <<= 1) {
        s  += __shfl_xor_sync(0xffffffffu, s, m);
        s2 += __shfl_xor_sync(0xffffffffu, s2, m);
      }
      float mu = s * (1.f / 128.f);
      float var = s2 * (1.f / 128.f) - mu * mu;
      float rinv = rsqrtf(var + 1e-5f);
      int row = ty * 8 + r;
#pragma unroll
      for (int c = 0; c < 8; ++c)
        sH[row * H + tx * 8 + c] =
            softplus_f((z[c] - mu) * rinv * g[c] + bt[c]);
    }
  }
  __syncthreads();

  // ---------------------- phi_e layer 2 ----------------------
#pragma unroll
  for (int r = 0; r < 8; ++r)
#pragma unroll
    for (int c = 0; c < 8; ++c) acc[r][c] = 0.f;
  gemm_tile<H, H, 16>(p.We2, sH, sB, acc, tx, ty, tid);
  {
    float bias[8];
#pragma unroll
    for (int c = 0; c < 8; ++c) bias[c] = p.be2[tx * 8 + c];
#pragma unroll
    for (int r = 0; r < 8; ++r)
#pragma unroll
      for (int c = 0; c < 8; ++c)
        sA[(ty * 8 + r) * H + tx * 8 + c] = softplus_f(acc[r][c] + bias[c]);
  }
  __syncthreads();

  // ---------------------- phi_e layer 3 ----------------------
#pragma unroll
  for (int r = 0; r < 8; ++r)
#pragma unroll
    for (int c = 0; c < 8; ++c) acc[r][c] = 0.f;
  gemm_tile<H, H, 16>(p.We3, sA, sB, acc, tx, ty, tid);
  {
    float bias[8];
#pragma unroll
    for (int c = 0; c < 8; ++c) bias[c] = p.be3[tx * 8 + c];
#pragma unroll
    for (int r = 0; r < 8; ++r) {
      int d = sDst[ty * 8 + r];
      float* gp = &g_mh[d * H + tx * 8];
#pragma unroll
      for (int c = 0; c < 8; ++c) atomicAdd(gp + c, acc[r][c] + bias[c]);
    }
  }
}

__global__ void __launch_bounds__(256, 1) node_kernel(NodeParams p) {
  float* sA   = smem_dyn;           // 128 * KHP
  float* sH   = sA + 128 * KHP;     // 128 * 128
  float* sB   = sH + 128 * H;       // 8 * 128
  float* sDen = sB + 8 * H;         // 128

  int tid = threadIdx.x;
  int tx = tid & 15, ty = tid >> 4;
  int n0 = blockIdx.x * 128;

  for (int i = tid; i < 128 * KHP; i += 256) sA[i] = 0.f;
  __syncthreads();
  if (tid < 128) {
    int n = n0 + tid;
    float den = 1.f, nrm = 0.f;
    if (n < NNODES) {
      den = fmaxf(g_cnt[n], 1.f);
      float mvx = g_mv[2 * n] / den + 1e-8f;
      float mvy = g_mv[2 * n + 1] / den + 1e-8f;
      nrm = sqrtf(mvx * mvx + mvy * mvy);
    }
    sDen[tid] = den;
    sA[tid * KHP + 192] = nrm;
  }
  __syncthreads();
  for (int i = tid; i < 128 * C; i += 256) {
    int r = i >> 6, c = i & 63;
    int n = n0 + r;
    if (n < NNODES) sA[r * KHP + c] = p.x[n * 64 + c];
  }
  for (int i = tid; i < 128 * H; i += 256) {
    int r = i >> 7, c = i & 127;
    int n = n0 + r;
    if (n < NNODES) sA[r * KHP + 64 + c] = g_mh[n * 128 + c] / sDen[r];
  }
  __syncthreads();

  float acc[8][8];
#pragma unroll
  for (int r = 0; r < 8; ++r)
#pragma unroll
    for (int c = 0; c < 8; ++c) acc[r][c] = 0.f;
  gemm_tile<KHP, KH, 25>(p.Wh1, sA, sB, acc, tx, ty, tid);
  {
    float bias[8], g[8], bt[8];
#pragma unroll
    for (int c = 0; c < 8; ++c) {
      int col = tx * 8 + c;
      bias[c] = p.bh1[col]; g[c] = p.gh1[col]; bt[c] = p.bth1[col];
    }
#pragma unroll
    for (int r = 0; r < 8; ++r) {
      float z[8], s = 0.f, s2 = 0.f;
#pragma unroll
      for (int c = 0; c < 8; ++c) {
        z[c] = acc[r][c] + bias[c];
        s += z[c]; s2 += z[c] * z[c];
      }
#pragma unroll
      for (int m = 1; m < 16; m <<= 1) {
        s  += __shfl_xor_sync(0xffffffffu, s, m);
        s2 += __shfl_xor_sync(0xffffffffu, s2, m);
      }
      float mu = s * (1.f / 128.f);
      float var = s2 * (1.f / 128.f) - mu * mu;
      float rinv = rsqrtf(var + 1e-5f);
      int row = ty * 8 + r;
#pragma unroll
      for (int c = 0; c < 8; ++c)
        sH[row * H + tx * 8 + c] =
            softplus_f((z[c] - mu) * rinv * g[c] + bt[c]);
    }
  }
  __syncthreads();

  // out = hu @ Wh2 + bh2 + x  (128 x 64)
  float acc2[8][4];
#pragma unroll
  for (int r = 0; r < 8; ++r)
#pragma unroll
    for (int c = 0; c < 4; ++c) acc2[r][c] = 0.f;
#pragma unroll 1
  for (int ch = 0; ch < 16; ++ch) {
    int k0 = ch * 8;
    if (tid < 128) {
      reinterpret_cast<float4*>(sB)[tid] =
          reinterpret_cast<const float4*>(p.Wh2)[(k0 + (tid >> 4)) * 16 +
                                                 (tid & 15)];
    }
    __syncthreads();
#pragma unroll
    for (int kk = 0; kk < 8; ++kk) {
      float a[8];
#pragma unroll
      for (int r = 0; r < 8; ++r) a[r] = sH[(ty * 8 + r) * H + k0 + kk];
      float4 b4 = reinterpret_cast<const float4*>(sB + kk * 64 + tx * 4)[0];
      float b[4] = {b4.x, b4.y, b4.z, b4.w};
#pragma unroll
      for (int r = 0; r < 8; ++r)
#pragma unroll
        for (int c = 0; c < 4; ++c) acc2[r][c] = fmaf(a[r], b[c], acc2[r][c]);
    }
    __syncthreads();
  }
  float bias2[4];
#pragma unroll
  for (int c = 0; c < 4; ++c) bias2[c] = p.bh2[tx * 4 + c];
#pragma unroll
  for (int r = 0; r < 8; ++r) {
    int n = n0 + ty * 8 + r;
    if (n < NNODES) {
#pragma unroll
      for (int c = 0; c < 4; ++c) {
        int col = tx * 4 + c;
        p.out[n * 64 + col] = p.x[n * 64 + col] + acc2[r][c] + bias2[c];
      }
    }
  }
}

extern "C" void kernel_launch(void* const* d_in, const int* in_sizes, int n_in,
                              void* d_out, int out_size) {
  EdgeParams ep;
  ep.x    = (const float*)d_in[0];
  ep.pos  = (const float*)d_in[1];
  ep.vel  = (const float*)d_in[2];
  ep.We1  = (const float*)d_in[3];
  ep.be1  = (const float*)d_in[4];
  ep.ge1  = (const float*)d_in[5];
  ep.bte1 = (const float*)d_in[6];
  ep.We2  = (const float*)d_in[7];
  ep.be2  = (const float*)d_in[8];
  ep.We3  = (const float*)d_in[9];
  ep.be3  = (const float*)d_in[10];
  ep.Wv1  = (const float*)d_in[11];
  ep.bv1  = (const float*)d_in[12];
  ep.gv1  = (const float*)d_in[13];
  ep.btv1 = (const float*)d_in[14];
  ep.Wv2  = (const float*)d_in[15];
  ep.bv2  = (const float*)d_in[16];
  ep.ei   = (const int*)d_in[23];

  NodeParams np;
  np.x    = ep.x;
  np.Wh1  = (const float*)d_in[17];
  np.bh1  = (const float*)d_in[18];
  np.gh1  = (const float*)d_in[19];
  np.bth1 = (const float*)d_in[20];
  np.Wh2  = (const float*)d_in[21];
  np.bh2  = (const float*)d_in[22];
  np.out  = (float*)d_out;

  int edge_smem = (ETILE * KF + ETILE * H + 8 * H + 2 * ETILE) * (int)sizeof(float) +
                  2 * ETILE * (int)sizeof(int);
  int node_smem = (128 * KHP + 128 * H + 8 * H + 128) * (int)sizeof(float);
  cudaFuncSetAttribute(edge_kernel, cudaFuncAttributeMaxDynamicSharedMemorySize,
                       edge_smem);
  cudaFuncSetAttribute(node_kernel, cudaFuncAttributeMaxDynamicSharedMemorySize,
                       node_smem);

  zero_kernel<<<(NNODES * H + 255) / 256, 256>>>();
  edge_kernel<<<NEDGES / ETILE, 256, edge_smem>>>(ep);
  node_kernel<<<(NNODES + 127) / 128, 256, node_smem>>>(np);
}

// round 5
// speedup vs baseline: 4.5062x; 4.5062x over previous
#include <cuda_runtime.h>
#include <cuda_fp16.h>
#include <cstdint>

// ---------------------------------------------------------------------------
// R4: mma.sync (HMMA) fp16 persistent edge kernel.
//   (tcgen05 is unavailable: harness emits compute_103 PTX, no 'a' target.)
//   - 148 persistent CTAs x 256 threads; 8 warps, each warp owns 16 edge rows.
//   - Weights We1/Wv1/We2/We3 (first 128 K-rows) as fp16 in swizzled smem,
//     loaded once per CTA. Activations fp16 in smem, fp32 accum in registers.
//   - Per 128-edge tile:
//       gather x[dst]|x[src] -> A (fp16)          [block sync]
//       E1 = A @ We1   -> +bias +rank5(fp32 feats) -> LN -> softplus -> B
//       V  = A @ Wv1   -> same -> dot Wv2 -> atomic g_mv / g_cnt
//       E2 = B @ We2   -> +bias -> softplus -> A   (per-warp rows only)
//       E3 = A @ We3   -> +bias -> atomic scatter g_mh
//     Geometric features (cols 128..132, up to 1.6e5) applied exactly in fp32
//     epilogue (fp16-overflow safe).
// Node kernel / zero kernel: fp32 (small), unchanged from R1 (passed).
// ---------------------------------------------------------------------------

namespace {
constexpr int NNODES = 20000;
constexpr int NEDGES = 640000;
constexpr int H      = 128;
constexpr int ETILE  = 128;
constexpr int NTILES = NEDGES / ETILE;   // 5000
constexpr int KH     = 193;
constexpr int KHP    = 200;

// smem byte offsets (tile bases 1024-aligned)
constexpr int OW_E1 = 0;
constexpr int OW_V1 = 32768;
constexpr int OW_E2 = 65536;
constexpr int OW_E3 = 98304;
constexpr int OACTA = 131072;
constexpr int OACTB = 163840;
constexpr int O_W5E = 196608;  // 5*128 fp32
constexpr int O_W5V = 199168;
constexpr int O_BE1 = 201728;
constexpr int O_GE1 = 202240;
constexpr int O_BTE1= 202752;
constexpr int O_BV1 = 203264;
constexpr int O_GV1 = 203776;
constexpr int O_BTV1= 204288;
constexpr int O_WV2 = 204800;
constexpr int O_BE2 = 205312;
constexpr int O_BE3 = 205824;
constexpr int O_FEAT= 206336;  // 128*5 fp32
constexpr int O_REL = 208896;  // 128*2 fp32
constexpr int O_DST = 209920;  // 128 int
constexpr int O_SRC = 210432;  // 128 int
constexpr int O_BV2 = 210944;
constexpr int EDGE_SMEM = 211072;
}  // namespace

__device__ float g_mh[NNODES * H];
__device__ float g_mv[NNODES * 2];
__device__ float g_cnt[NNODES];

struct EdgeParams {
  const float *x, *pos, *vel;
  const float *We1, *be1, *ge1, *bte1, *We2, *be2, *We3, *be3;
  const float *Wv1, *bv1, *gv1, *btv1, *Wv2, *bv2;
  const int   *ei;
};
struct NodeParams {
  const float *x;
  const float *Wh1, *bh1, *gh1, *bth1, *Wh2, *bh2;
  float       *out;
};

// ------------------------------- helpers -----------------------------------
__device__ __forceinline__ uint32_t smem_u32(const void* p) {
  uint32_t a;
  asm("{ .reg .u64 t; cvta.to.shared.u64 t, %1; cvt.u32.u64 %0, t; }"
      : "=r"(a) : "l"(p));
  return a;
}
__device__ __forceinline__ void ldsm4(uint32_t& a0, uint32_t& a1, uint32_t& a2,
                                      uint32_t& a3, uint32_t addr) {
  asm volatile(
      "ldmatrix.sync.aligned.m8n8.x4.shared.b16 {%0,%1,%2,%3}, [%4];"
      : "=r"(a0), "=r"(a1), "=r"(a2), "=r"(a3) : "r"(addr));
}
__device__ __forceinline__ void ldsm4t(uint32_t& a0, uint32_t& a1, uint32_t& a2,
                                       uint32_t& a3, uint32_t addr) {
  asm volatile(
      "ldmatrix.sync.aligned.m8n8.x4.trans.shared.b16 {%0,%1,%2,%3}, [%4];"
      : "=r"(a0), "=r"(a1), "=r"(a2), "=r"(a3) : "r"(addr));
}
__device__ __forceinline__ void mma16816(float* c, uint32_t a0, uint32_t a1,
                                         uint32_t a2, uint32_t a3, uint32_t b0,
                                         uint32_t b1) {
  asm volatile(
      "mma.sync.aligned.m16n8k16.row.col.f32.f16.f16.f32 "
      "{%0,%1,%2,%3}, {%4,%5,%6,%7}, {%8,%9}, {%0,%1,%2,%3};"
      : "+f"(c[0]), "+f"(c[1]), "+f"(c[2]), "+f"(c[3])
      : "r"(a0), "r"(a1), "r"(a2), "r"(a3), "r"(b0), "r"(b1));
}
// byte offset in a 128x128 fp16 tile: 256B rows, 16B-chunk xor swizzle
__device__ __forceinline__ uint32_t swb(int row, int col) {
  return (uint32_t)row * 256u + (uint32_t)((((col >> 3) ^ (row & 7)) & 15) << 4) +
         (uint32_t)((col & 7) << 1);
}
__device__ __forceinline__ uint32_t h2pack(float a, float b) {
  __half2 h = __floats2half2_rn(a, b);
  return (uint32_t)__half_as_ushort(__low2half(h)) |
         ((uint32_t)__half_as_ushort(__high2half(h)) << 16);
}
__device__ __forceinline__ float softplus_f(float v) {
  return fmaxf(v, 0.f) + __logf(1.f + __expf(-fabsf(v)));
}

// acc[16][4] = rows [m0..m0+15] of (Atile @ Wtile), K = 128.
__device__ __forceinline__ void warp_gemm(uint32_t smA, uint32_t smW, int m0,
                                          int lane, float acc[16][4]) {
#pragma unroll
  for (int f = 0; f < 16; ++f)
#pragma unroll
    for (int e = 0; e < 4; ++e) acc[f][e] = 0.f;

  const int mid = lane >> 3;     // which 8x8 matrix this lane addresses
  const int wi  = lane & 7;
  const int arow = m0 + wi + (mid & 1) * 8;
  const uint32_t arow_base = smA + (uint32_t)arow * 256u;
  const int ar7 = arow & 7;

#pragma unroll
  for (int k = 0; k < 8; ++k) {
    const int k0 = k * 16;
    // ---- A fragment (16x16) ----
    int cha = (k0 >> 3) + (mid >> 1);
    uint32_t a0, a1, a2, a3;
    ldsm4(a0, a1, a2, a3, arow_base + (uint32_t)(((cha ^ ar7) & 15) << 4));
    // ---- B fragments: 8 x (16x16) covering n = 0..127 ----
    const int krow = k0 + wi + (mid & 1) * 8;
    const uint32_t brow_base = smW + (uint32_t)krow * 256u;
    const int kr7 = krow & 7;
#pragma unroll
    for (int nf2 = 0; nf2 < 8; ++nf2) {
      int chb = (nf2 << 1) + (mid >> 1);
      uint32_t b0, b1, b2, b3;
      ldsm4t(b0, b1, b2, b3, brow_base + (uint32_t)(((chb ^ kr7) & 15) << 4));
      mma16816(acc[2 * nf2],     a0, a1, a2, a3, b0, b1);
      mma16816(acc[2 * nf2 + 1], a0, a1, a2, a3, b2, b3);
    }
  }
}

__global__ void zero_kernel() {
  int i = blockIdx.x * 256 + threadIdx.x;
  if (i < NNODES * H) g_mh[i] = 0.f;
  if (i < NNODES * 2) g_mv[i] = 0.f;
  if (i < NNODES)     g_cnt[i] = 0.f;
}

// ------------------------------ edge kernel --------------------------------
__global__ void __launch_bounds__(256, 1) edge_kernel(EdgeParams p) {
  extern __shared__ __align__(1024) char sm[];
  const int tid  = threadIdx.x;
  const int wid  = tid >> 5;
  const int lane = tid & 31;

  // ---------------- prologue: weights / params into smem -----------------
  {
    const float* Wm[4] = {p.We1, p.Wv1, p.We2, p.We3};
#pragma unroll 1
    for (int m = 0; m < 4; ++m) {
      const float* W = Wm[m];
      char* base = sm + m * 32768;
      for (int i = tid; i < 4096; i += 256) {
        int k  = i >> 5;
        int c4 = (i & 31) << 2;
        float4 w = *(const float4*)(W + k * 128 + c4);
        uint2 pk;
        pk.x = h2pack(w.x, w.y);
        pk.y = h2pack(w.z, w.w);
        *(uint2*)(base + swb(k, c4)) = pk;
      }
    }
    for (int i = tid; i < 640; i += 256) {
      int j = i >> 7, c = i & 127;
      ((float*)(sm + O_W5E))[i] = p.We1[(128 + j) * 128 + c];
      ((float*)(sm + O_W5V))[i] = p.Wv1[(128 + j) * 128 + c];
    }
    if (tid < 128) {
      ((float*)(sm + O_BE1))[tid]  = p.be1[tid];
      ((float*)(sm + O_GE1))[tid]  = p.ge1[tid];
      ((float*)(sm + O_BTE1))[tid] = p.bte1[tid];
      ((float*)(sm + O_BV1))[tid]  = p.bv1[tid];
      ((float*)(sm + O_GV1))[tid]  = p.gv1[tid];
      ((float*)(sm + O_BTV1))[tid] = p.btv1[tid];
      ((float*)(sm + O_WV2))[tid]  = p.Wv2[tid];
      ((float*)(sm + O_BE2))[tid]  = p.be2[tid];
      ((float*)(sm + O_BE3))[tid]  = p.be3[tid];
    }
    if (tid == 0) ((float*)(sm + O_BV2))[0] = p.bv2[0];
  }
  __syncthreads();

  const uint32_t smb  = smem_u32(sm);
  const uint32_t bufA = smb + OACTA;
  const uint32_t bufB = smb + OACTB;
  const uint32_t wE1  = smb + OW_E1;
  const uint32_t wV1  = smb + OW_V1;
  const uint32_t wE2  = smb + OW_E2;
  const uint32_t wE3  = smb + OW_E3;

  int*   sDst  = (int*)(sm + O_DST);
  int*   sSrc  = (int*)(sm + O_SRC);
  float* sRel  = (float*)(sm + O_REL);
  float* sFeat = (float*)(sm + O_FEAT);
  const float* w5e = (const float*)(sm + O_W5E);
  const float* w5v = (const float*)(sm + O_W5V);
  const float* cBE1 = (const float*)(sm + O_BE1);
  const float* cGE1 = (const float*)(sm + O_GE1);
  const float* cBT1 = (const float*)(sm + O_BTE1);
  const float* cBV1 = (const float*)(sm + O_BV1);
  const float* cGV1 = (const float*)(sm + O_GV1);
  const float* cBTV = (const float*)(sm + O_BTV1);
  const float* cWV2 = (const float*)(sm + O_WV2);
  const float* cBE2 = (const float*)(sm + O_BE2);
  const float* cBE3 = (const float*)(sm + O_BE3);

  const int g  = lane >> 2;       // quad group id = row within 8
  const int q  = lane & 3;
  const int m0 = wid * 16;
  const int rA = m0 + g;          // this thread's two output rows
  const int rB = rA + 8;

  float acc[16][4];

#pragma unroll 1
  for (int tile = blockIdx.x; tile < NTILES; tile += gridDim.x) {
    __syncthreads();  // bufA/sFeat safe to overwrite
    const int e0 = tile * ETILE;

    // ------------- geometry + gather into fp16 A tile -------------
    if (tid < ETILE) {
      int e = e0 + tid;
      int s = p.ei[e], d = p.ei[NEDGES + e];
      sSrc[tid] = s;
      sDst[tid] = d;
      float2 ps = ((const float2*)p.pos)[s], pd = ((const float2*)p.pos)[d];
      float2 vs = ((const float2*)p.vel)[s], vd = ((const float2*)p.vel)[d];
      float rpx = ps.x - pd.x, rpy = ps.y - pd.y;
      float rvx = vs.x - vd.x, rvy = vs.y - vd.y;
      float dist = rpx * rpx + rpy * rpy;
      float dvr  = rvx * rpx + rvy * rpy;
      float r2   = fminf(1.f / (dist + 0.05f), 20.f);
      float r6   = fminf(r2 * r2 * r2, 400.f);
      float r12  = fminf(r6 * r6, 160000.f);
      sFeat[tid * 5 + 0] = dist;
      sFeat[tid * 5 + 1] = dvr;
      sFeat[tid * 5 + 2] = r2;
      sFeat[tid * 5 + 3] = r6;
      sFeat[tid * 5 + 4] = r12;
      sRel[2 * tid]     = rpx;
      sRel[2 * tid + 1] = rpy;
    }
    __syncthreads();
#pragma unroll 1
    for (int i = tid; i < ETILE * 32; i += 256) {
      int e = i >> 5, qq = i & 31;
      int half = qq >> 4, c4 = qq & 15;
      int node = half ? sSrc[e] : sDst[e];
      float4 v = ((const float4*)p.x)[node * 16 + c4];
      uint2 pk;
      pk.x = h2pack(v.x, v.y);
      pk.y = h2pack(v.z, v.w);
      *(uint2*)(sm + OACTA + swb(e, half * 64 + c4 * 4)) = pk;
    }
    __syncthreads();

    // per-row features for this thread's two rows
    float fA[5], fB[5];
#pragma unroll
    for (int j = 0; j < 5; ++j) {
      fA[j] = sFeat[rA * 5 + j];
      fB[j] = sFeat[rB * 5 + j];
    }

    // ================= stage 1a: E1 = A @ We1 =================
    warp_gemm(bufA, wE1, m0, lane, acc);
    {
      float sa = 0.f, s2a = 0.f, sb = 0.f, s2b = 0.f;
#pragma unroll
      for (int f = 0; f < 16; ++f) {
#pragma unroll
        for (int t = 0; t < 2; ++t) {
          int c = 8 * f + 2 * q + t;
          float w0 = w5e[c], w1 = w5e[128 + c], w2 = w5e[256 + c],
                w3 = w5e[384 + c], w4 = w5e[512 + c];
          float bb = cBE1[c];
          float za = acc[f][t] + bb + fA[0] * w0 + fA[1] * w1 + fA[2] * w2 +
                     fA[3] * w3 + fA[4] * w4;
          float zb = acc[f][2 + t] + bb + fB[0] * w0 + fB[1] * w1 +
                     fB[2] * w2 + fB[3] * w3 + fB[4] * w4;
          acc[f][t] = za;
          acc[f][2 + t] = zb;
          sa += za; s2a = fmaf(za, za, s2a);
          sb += zb; s2b = fmaf(zb, zb, s2b);
        }
      }
#pragma unroll
      for (int m = 1; m < 4; m <<= 1) {
        sa  += __shfl_xor_sync(0xffffffffu, sa, m);
        s2a += __shfl_xor_sync(0xffffffffu, s2a, m);
        sb  += __shfl_xor_sync(0xffffffffu, sb, m);
        s2b += __shfl_xor_sync(0xffffffffu, s2b, m);
      }
      float mua = sa * (1.f / 128.f);
      float ria = rsqrtf(s2a * (1.f / 128.f) - mua * mua + 1e-5f);
      float mub = sb * (1.f / 128.f);
      float rib = rsqrtf(s2b * (1.f / 128.f) - mub * mub + 1e-5f);
#pragma unroll
      for (int f = 0; f < 16; ++f) {
        int c0 = 8 * f + 2 * q;
        float ha0 = softplus_f((acc[f][0] - mua) * ria * cGE1[c0] + cBT1[c0]);
        float ha1 = softplus_f((acc[f][1] - mua) * ria * cGE1[c0 + 1] + cBT1[c0 + 1]);
        float hb0 = softplus_f((acc[f][2] - mub) * rib * cGE1[c0] + cBT1[c0]);
        float hb1 = softplus_f((acc[f][3] - mub) * rib * cGE1[c0 + 1] + cBT1[c0 + 1]);
        *(uint32_t*)(sm + OACTB + swb(rA, c0)) = h2pack(ha0, ha1);
        *(uint32_t*)(sm + OACTB + swb(rB, c0)) = h2pack(hb0, hb1);
      }
    }

    // ================= stage 1b: V = A @ Wv1 =================
    warp_gemm(bufA, wV1, m0, lane, acc);
    {
      float sa = 0.f, s2a = 0.f, sb = 0.f, s2b = 0.f;
#pragma unroll
      for (int f = 0; f < 16; ++f) {
#pragma unroll
        for (int t = 0; t < 2; ++t) {
          int c = 8 * f + 2 * q + t;
          float w0 = w5v[c], w1 = w5v[128 + c], w2 = w5v[256 + c],
                w3 = w5v[384 + c], w4 = w5v[512 + c];
          float bb = cBV1[c];
          float za = acc[f][t] + bb + fA[0] * w0 + fA[1] * w1 + fA[2] * w2 +
                     fA[3] * w3 + fA[4] * w4;
          float zb = acc[f][2 + t] + bb + fB[0] * w0 + fB[1] * w1 +
                     fB[2] * w2 + fB[3] * w3 + fB[4] * w4;
          acc[f][t] = za;
          acc[f][2 + t] = zb;
          sa += za; s2a = fmaf(za, za, s2a);
          sb += zb; s2b = fmaf(zb, zb, s2b);
        }
      }
#pragma unroll
      for (int m = 1; m < 4; m <<= 1) {
        sa  += __shfl_xor_sync(0xffffffffu, sa, m);
        s2a += __shfl_xor_sync(0xffffffffu, s2a, m);
        sb  += __shfl_xor_sync(0xffffffffu, sb, m);
        s2b += __shfl_xor_sync(0xffffffffu, s2b, m);
      }
      float mua = sa * (1.f / 128.f);
      float ria = rsqrtf(s2a * (1.f / 128.f) - mua * mua + 1e-5f);
      float mub = sb * (1.f / 128.f);
      float rib = rsqrtf(s2b * (1.f / 128.f) - mub * mub + 1e-5f);
      float va = 0.f, vb = 0.f;
#pragma unroll
      for (int f = 0; f < 16; ++f) {
#pragma unroll
        for (int t = 0; t < 2; ++t) {
          int c = 8 * f + 2 * q + t;
          float gv = cGV1[c], bt = cBTV[c], wv = cWV2[c];
          va += softplus_f((acc[f][t] - mua) * ria * gv + bt) * wv;
          vb += softplus_f((acc[f][2 + t] - mub) * rib * gv + bt) * wv;
        }
      }
#pragma unroll
      for (int m = 1; m < 4; m <<= 1) {
        va += __shfl_xor_sync(0xffffffffu, va, m);
        vb += __shfl_xor_sync(0xffffffffu, vb, m);
      }
      if (q == 0) {
        float bv2v = ((const float*)(sm + O_BV2))[0];
        int dA = sDst[rA];
        float vwa = va + bv2v;
        atomicAdd(&g_mv[2 * dA],     vwa * sRel[2 * rA]);
        atomicAdd(&g_mv[2 * dA + 1], vwa * sRel[2 * rA + 1]);
        atomicAdd(&g_cnt[dA], 1.f);
        int dB = sDst[rB];
        float vwb = vb + bv2v;
        atomicAdd(&g_mv[2 * dB],     vwb * sRel[2 * rB]);
        atomicAdd(&g_mv[2 * dB + 1], vwb * sRel[2 * rB + 1]);
        atomicAdd(&g_cnt[dB], 1.f);
      }
    }

    // ================= stage 2: E2 = H1 @ We2 =================
    __syncwarp();  // own-row H1 stores visible to own-warp ldmatrix
    warp_gemm(bufB, wE2, m0, lane, acc);
    {
#pragma unroll
      for (int f = 0; f < 16; ++f) {
        int c0 = 8 * f + 2 * q;
        float b0 = cBE2[c0], b1 = cBE2[c0 + 1];
        float ha0 = softplus_f(acc[f][0] + b0);
        float ha1 = softplus_f(acc[f][1] + b1);
        float hb0 = softplus_f(acc[f][2] + b0);
        float hb1 = softplus_f(acc[f][3] + b1);
        *(uint32_t*)(sm + OACTA + swb(rA, c0)) = h2pack(ha0, ha1);
        *(uint32_t*)(sm + OACTA + swb(rB, c0)) = h2pack(hb0, hb1);
      }
    }

    // ================= stage 3: E3 = H2 @ We3 -> scatter =================
    __syncwarp();
    warp_gemm(bufA, wE3, m0, lane, acc);
    {
      int dA = sDst[rA], dB = sDst[rB];
      float* gpa = g_mh + dA * H;
      float* gpb = g_mh + dB * H;
#pragma unroll
      for (int f = 0; f < 16; ++f) {
        int c0 = 8 * f + 2 * q;
        float b0 = cBE3[c0], b1 = cBE3[c0 + 1];
        atomicAdd(gpa + c0,     acc[f][0] + b0);
        atomicAdd(gpa + c0 + 1, acc[f][1] + b1);
        atomicAdd(gpb + c0,     acc[f][2] + b0);
        atomicAdd(gpb + c0 + 1, acc[f][3] + b1);
      }
    }
  }
}

// ------------------------------ node kernel --------------------------------
template <int STRIDE, int KACT, int NCHUNK>
__device__ __forceinline__ void gemm_tile(const float* __restrict__ W,
                                          const float* sA_, float* sB_,
                                          float acc[8][8], int tx, int ty,
                                          int tid) {
  int wrow = tid >> 5, wc4 = tid & 31;
  float4 v;
  {
    int k = wrow;
    v = (k < KACT) ? reinterpret_cast<const float4*>(W)[k * 32 + wc4]
                   : make_float4(0.f, 0.f, 0.f, 0.f);
  }
#pragma unroll 1
  for (int ch = 0; ch < NCHUNK; ++ch) {
    reinterpret_cast<float4*>(sB_)[tid] = v;
    __syncthreads();
    if (ch + 1 < NCHUNK) {
      int k = (ch + 1) * 8 + wrow;
      v = (k < KACT) ? reinterpret_cast<const float4*>(W)[k * 32 + wc4]
                     : make_float4(0.f, 0.f, 0.f, 0.f);
    }
    int k0 = ch * 8;
#pragma unroll
    for (int kk = 0; kk < 8; ++kk) {
      float a[8];
#pragma unroll
      for (int r = 0; r < 8; ++r) a[r] = sA_[(ty * 8 + r) * STRIDE + k0 + kk];
      const float4* bp = reinterpret_cast<const float4*>(sB_ + kk * 128 + tx * 8);
      float4 b0 = bp[0], b1 = bp[1];
      float b[8] = {b0.x, b0.y, b0.z, b0.w, b1.x, b1.y, b1.z, b1.w};
#pragma unroll
      for (int r = 0; r < 8; ++r)
#pragma unroll
        for (int c = 0; c < 8; ++c) acc[r][c] = fmaf(a[r], b[c], acc[r][c]);
    }
    __syncthreads();
  }
}

__global__ void __launch_bounds__(256, 1) node_kernel(NodeParams p) {
  extern __shared__ float smem_dyn[];
  float* sA   = smem_dyn;           // 128 * KHP
  float* sH   = sA + 128 * KHP;     // 128 * 128
  float* sB   = sH + 128 * H;       // 8 * 128
  float* sDen = sB + 8 * H;         // 128

  int tid = threadIdx.x;
  int tx = tid & 15, ty = tid >> 4;
  int n0 = blockIdx.x * 128;

  for (int i = tid; i < 128 * KHP; i += 256) sA[i] = 0.f;
  __syncthreads();
  if (tid < 128) {
    int n = n0 + tid;
    float den = 1.f, nrm = 0.f;
    if (n < NNODES) {
      den = fmaxf(g_cnt[n], 1.f);
      float mvx = g_mv[2 * n] / den + 1e-8f;
      float mvy = g_mv[2 * n + 1] / den + 1e-8f;
      nrm = sqrtf(mvx * mvx + mvy * mvy);
    }
    sDen[tid] = den;
    sA[tid * KHP + 192] = nrm;
  }
  __syncthreads();
  for (int i = tid; i < 128 * 64; i += 256) {
    int r = i >> 6, c = i & 63;
    int n = n0 + r;
    if (n < NNODES) sA[r * KHP + c] = p.x[n * 64 + c];
  }
  for (int i = tid; i < 128 * H; i += 256) {
    int r = i >> 7, c = i & 127;
    int n = n0 + r;
    if (n < NNODES) sA[r * KHP + 64 + c] = g_mh[n * 128 + c] / sDen[r];
  }
  __syncthreads();

  float acc[8][8];
#pragma unroll
  for (int r = 0; r < 8; ++r)
#pragma unroll
    for (int c = 0; c < 8; ++c) acc[r][c] = 0.f;
  gemm_tile<KHP, KH, 25>(p.Wh1, sA, sB, acc, tx, ty, tid);
  {
    float bias[8], g[8], bt[8];
#pragma unroll
    for (int c = 0; c < 8; ++c) {
      int col = tx * 8 + c;
      bias[c] = p.bh1[col]; g[c] = p.gh1[col]; bt[c] = p.bth1[col];
    }
#pragma unroll
    for (int r = 0; r < 8; ++r) {
      float z[8], s = 0.f, s2 = 0.f;
#pragma unroll
      for (int c = 0; c < 8; ++c) {
        z[c] = acc[r][c] + bias[c];
        s += z[c]; s2 += z[c] * z[c];
      }
#pragma unroll
      for (int m = 1; m < 16; m <<= 1) {
        s  += __shfl_xor_sync(0xffffffffu, s, m);
        s2 += __shfl_xor_sync(0xffffffffu, s2, m);
      }
      float mu = s * (1.f / 128.f);
      float var = s2 * (1.f / 128.f) - mu * mu;
      float rinv = rsqrtf(var + 1e-5f);
      int row = ty * 8 + r;
#pragma unroll
      for (int c = 0; c < 8; ++c)
        sH[row * H + tx * 8 + c] =
            softplus_f((z[c] - mu) * rinv * g[c] + bt[c]);
    }
  }
  __syncthreads();

  float acc2[8][4];
#pragma unroll
  for (int r = 0; r < 8; ++r)
#pragma unroll
    for (int c = 0; c < 4; ++c) acc2[r][c] = 0.f;
#pragma unroll 1
  for (int ch = 0; ch < 16; ++ch) {
    int k0 = ch * 8;
    if (tid < 128) {
      reinterpret_cast<float4*>(sB)[tid] =
          reinterpret_cast<const float4*>(p.Wh2)[(k0 + (tid >> 4)) * 16 +
                                                 (tid & 15)];
    }
    __syncthreads();
#pragma unroll
    for (int kk = 0; kk < 8; ++kk) {
      float a[8];
#pragma unroll
      for (int r = 0; r < 8; ++r) a[r] = sH[(ty * 8 + r) * H + k0 + kk];
      float4 b4 = reinterpret_cast<const float4*>(sB + kk * 64 + tx * 4)[0];
      float b[4] = {b4.x, b4.y, b4.z, b4.w};
#pragma unroll
      for (int r = 0; r < 8; ++r)
#pragma unroll
        for (int c = 0; c < 4; ++c) acc2[r][c] = fmaf(a[r], b[c], acc2[r][c]);
    }
    __syncthreads();
  }
  float bias2[4];
#pragma unroll
  for (int c = 0; c < 4; ++c) bias2[c] = p.bh2[tx * 4 + c];
#pragma unroll
  for (int r = 0; r < 8; ++r) {
    int n = n0 + ty * 8 + r;
    if (n < NNODES) {
#pragma unroll
      for (int c = 0; c < 4; ++c) {
        int col = tx * 4 + c;
        p.out[n * 64 + col] = p.x[n * 64 + col] + acc2[r][c] + bias2[c];
      }
    }
  }
}

// ------------------------------ launch -------------------------------------
extern "C" void kernel_launch(void* const* d_in, const int* in_sizes, int n_in,
                              void* d_out, int out_size) {
  EdgeParams ep;
  ep.x    = (const float*)d_in[0];
  ep.pos  = (const float*)d_in[1];
  ep.vel  = (const float*)d_in[2];
  ep.We1  = (const float*)d_in[3];
  ep.be1  = (const float*)d_in[4];
  ep.ge1  = (const float*)d_in[5];
  ep.bte1 = (const float*)d_in[6];
  ep.We2  = (const float*)d_in[7];
  ep.be2  = (const float*)d_in[8];
  ep.We3  = (const float*)d_in[9];
  ep.be3  = (const float*)d_in[10];
  ep.Wv1  = (const float*)d_in[11];
  ep.bv1  = (const float*)d_in[12];
  ep.gv1  = (const float*)d_in[13];
  ep.btv1 = (const float*)d_in[14];
  ep.Wv2  = (const float*)d_in[15];
  ep.bv2  = (const float*)d_in[16];
  ep.ei   = (const int*)d_in[23];

  NodeParams np;
  np.x    = ep.x;
  np.Wh1  = (const float*)d_in[17];
  np.bh1  = (const float*)d_in[18];
  np.gh1  = (const float*)d_in[19];
  np.bth1 = (const float*)d_in[20];
  np.Wh2  = (const float*)d_in[21];
  np.bh2  = (const float*)d_in[22];
  np.out  = (float*)d_out;

  int node_smem = (128 * KHP + 128 * H + 8 * H + 128) * (int)sizeof(float);
  cudaFuncSetAttribute(edge_kernel, cudaFuncAttributeMaxDynamicSharedMemorySize,
                       EDGE_SMEM);
  cudaFuncSetAttribute(node_kernel, cudaFuncAttributeMaxDynamicSharedMemorySize,
                       node_smem);

  zero_kernel<<<(NNODES * H + 255) / 256, 256>>>();
  edge_kernel<<<148, 256, EDGE_SMEM>>>(ep);
  node_kernel<<<(NNODES + 127) / 128, 256, node_smem>>>(np);
}

// round 6
// speedup vs baseline: 5.1246x; 1.1372x over previous
#include <cuda_runtime.h>
#include <cuda_fp16.h>
#include <cstdint>

// ---------------------------------------------------------------------------
// R5: R4 (HMMA fp16 persistent edge kernel) +
//   - red.global.add.v4.f32 scatter for g_mh (shfl pair-exchange -> 4 contig
//     cols per thread), red.v2 for g_mv  => 4x fewer RED ops
//   - batched register gather (MLP=16) to hide L2 latency
// ---------------------------------------------------------------------------

namespace {
constexpr int NNODES = 20000;
constexpr int NEDGES = 640000;
constexpr int H      = 128;
constexpr int ETILE  = 128;
constexpr int NTILES = NEDGES / ETILE;   // 5000
constexpr int KH     = 193;
constexpr int KHP    = 200;

constexpr int OW_E1 = 0;
constexpr int OW_V1 = 32768;
constexpr int OW_E2 = 65536;
constexpr int OW_E3 = 98304;
constexpr int OACTA = 131072;
constexpr int OACTB = 163840;
constexpr int O_W5E = 196608;  // 5*128 fp32
constexpr int O_W5V = 199168;
constexpr int O_BE1 = 201728;
constexpr int O_GE1 = 202240;
constexpr int O_BTE1= 202752;
constexpr int O_BV1 = 203264;
constexpr int O_GV1 = 203776;
constexpr int O_BTV1= 204288;
constexpr int O_WV2 = 204800;
constexpr int O_BE2 = 205312;
constexpr int O_BE3 = 205824;
constexpr int O_FEAT= 206336;  // 128*5 fp32
constexpr int O_REL = 208896;  // 128*2 fp32
constexpr int O_DST = 209920;  // 128 int
constexpr int O_SRC = 210432;  // 128 int
constexpr int O_BV2 = 210944;
constexpr int EDGE_SMEM = 211072;
}  // namespace

__device__ __align__(16) float g_mh[NNODES * H];
__device__ __align__(16) float g_mv[NNODES * 2];
__device__ float g_cnt[NNODES];

struct EdgeParams {
  const float *x, *pos, *vel;
  const float *We1, *be1, *ge1, *bte1, *We2, *be2, *We3, *be3;
  const float *Wv1, *bv1, *gv1, *btv1, *Wv2, *bv2;
  const int   *ei;
};
struct NodeParams {
  const float *x;
  const float *Wh1, *bh1, *gh1, *bth1, *Wh2, *bh2;
  float       *out;
};

// ------------------------------- helpers -----------------------------------
__device__ __forceinline__ uint32_t smem_u32(const void* p) {
  uint32_t a;
  asm("{ .reg .u64 t; cvta.to.shared.u64 t, %1; cvt.u32.u64 %0, t; }"
      : "=r"(a) : "l"(p));
  return a;
}
__device__ __forceinline__ void ldsm4(uint32_t& a0, uint32_t& a1, uint32_t& a2,
                                      uint32_t& a3, uint32_t addr) {
  asm volatile(
      "ldmatrix.sync.aligned.m8n8.x4.shared.b16 {%0,%1,%2,%3}, [%4];"
      : "=r"(a0), "=r"(a1), "=r"(a2), "=r"(a3) : "r"(addr));
}
__device__ __forceinline__ void ldsm4t(uint32_t& a0, uint32_t& a1, uint32_t& a2,
                                       uint32_t& a3, uint32_t addr) {
  asm volatile(
      "ldmatrix.sync.aligned.m8n8.x4.trans.shared.b16 {%0,%1,%2,%3}, [%4];"
      : "=r"(a0), "=r"(a1), "=r"(a2), "=r"(a3) : "r"(addr));
}
__device__ __forceinline__ void mma16816(float* c, uint32_t a0, uint32_t a1,
                                         uint32_t a2, uint32_t a3, uint32_t b0,
                                         uint32_t b1) {
  asm volatile(
      "mma.sync.aligned.m16n8k16.row.col.f32.f16.f16.f32 "
      "{%0,%1,%2,%3}, {%4,%5,%6,%7}, {%8,%9}, {%0,%1,%2,%3};"
      : "+f"(c[0]), "+f"(c[1]), "+f"(c[2]), "+f"(c[3])
      : "r"(a0), "r"(a1), "r"(a2), "r"(a3), "r"(b0), "r"(b1));
}
__device__ __forceinline__ void red4(float* p, float a, float b, float c,
                                     float d) {
  asm volatile("red.global.add.v4.f32 [%0], {%1,%2,%3,%4};"
               :: "l"(p), "f"(a), "f"(b), "f"(c), "f"(d) : "memory");
}
__device__ __forceinline__ void red2(float* p, float a, float b) {
  asm volatile("red.global.add.v2.f32 [%0], {%1,%2};"
               :: "l"(p), "f"(a), "f"(b) : "memory");
}
// byte offset in a 128x128 fp16 tile: 256B rows, 16B-chunk xor swizzle
__device__ __forceinline__ uint32_t swb(int row, int col) {
  return (uint32_t)row * 256u + (uint32_t)((((col >> 3) ^ (row & 7)) & 15) << 4) +
         (uint32_t)((col & 7) << 1);
}
__device__ __forceinline__ uint32_t h2pack(float a, float b) {
  __half2 h = __floats2half2_rn(a, b);
  return (uint32_t)__half_as_ushort(__low2half(h)) |
         ((uint32_t)__half_as_ushort(__high2half(h)) << 16);
}
__device__ __forceinline__ float softplus_f(float v) {
  return fmaxf(v, 0.f) + __logf(1.f + __expf(-fabsf(v)));
}

// acc[16][4] = rows [m0..m0+15] of (Atile @ Wtile), K = 128.
__device__ __forceinline__ void warp_gemm(uint32_t smA, uint32_t smW, int m0,
                                          int lane, float acc[16][4]) {
#pragma unroll
  for (int f = 0; f < 16; ++f)
#pragma unroll
    for (int e = 0; e < 4; ++e) acc[f][e] = 0.f;

  const int mid = lane >> 3;
  const int wi  = lane & 7;
  const int arow = m0 + wi + (mid & 1) * 8;
  const uint32_t arow_base = smA + (uint32_t)arow * 256u;
  const int ar7 = arow & 7;

#pragma unroll
  for (int k = 0; k < 8; ++k) {
    const int k0 = k * 16;
    int cha = (k0 >> 3) + (mid >> 1);
    uint32_t a0, a1, a2, a3;
    ldsm4(a0, a1, a2, a3, arow_base + (uint32_t)(((cha ^ ar7) & 15) << 4));
    const int krow = k0 + wi + (mid & 1) * 8;
    const uint32_t brow_base = smW + (uint32_t)krow * 256u;
    const int kr7 = krow & 7;
#pragma unroll
    for (int nf2 = 0; nf2 < 8; ++nf2) {
      int chb = (nf2 << 1) + (mid >> 1);
      uint32_t b0, b1, b2, b3;
      ldsm4t(b0, b1, b2, b3, brow_base + (uint32_t)(((chb ^ kr7) & 15) << 4));
      mma16816(acc[2 * nf2],     a0, a1, a2, a3, b0, b1);
      mma16816(acc[2 * nf2 + 1], a0, a1, a2, a3, b2, b3);
    }
  }
}

__global__ void zero_kernel() {
  int i = blockIdx.x * 256 + threadIdx.x;
  if (i < NNODES * H) g_mh[i] = 0.f;
  if (i < NNODES * 2) g_mv[i] = 0.f;
  if (i < NNODES)     g_cnt[i] = 0.f;
}

// ------------------------------ edge kernel --------------------------------
__global__ void __launch_bounds__(256, 1) edge_kernel(EdgeParams p) {
  extern __shared__ __align__(1024) char sm[];
  const int tid  = threadIdx.x;
  const int wid  = tid >> 5;
  const int lane = tid & 31;

  // ---------------- prologue -----------------
  {
    const float* Wm[4] = {p.We1, p.Wv1, p.We2, p.We3};
#pragma unroll 1
    for (int m = 0; m < 4; ++m) {
      const float* W = Wm[m];
      char* base = sm + m * 32768;
      for (int i = tid; i < 4096; i += 256) {
        int k  = i >> 5;
        int c4 = (i & 31) << 2;
        float4 w = *(const float4*)(W + k * 128 + c4);
        uint2 pk;
        pk.x = h2pack(w.x, w.y);
        pk.y = h2pack(w.z, w.w);
        *(uint2*)(base + swb(k, c4)) = pk;
      }
    }
    for (int i = tid; i < 640; i += 256) {
      int j = i >> 7, c = i & 127;
      ((float*)(sm + O_W5E))[i] = p.We1[(128 + j) * 128 + c];
      ((float*)(sm + O_W5V))[i] = p.Wv1[(128 + j) * 128 + c];
    }
    if (tid < 128) {
      ((float*)(sm + O_BE1))[tid]  = p.be1[tid];
      ((float*)(sm + O_GE1))[tid]  = p.ge1[tid];
      ((float*)(sm + O_BTE1))[tid] = p.bte1[tid];
      ((float*)(sm + O_BV1))[tid]  = p.bv1[tid];
      ((float*)(sm + O_GV1))[tid]  = p.gv1[tid];
      ((float*)(sm + O_BTV1))[tid] = p.btv1[tid];
      ((float*)(sm + O_WV2))[tid]  = p.Wv2[tid];
      ((float*)(sm + O_BE2))[tid]  = p.be2[tid];
      ((float*)(sm + O_BE3))[tid]  = p.be3[tid];
    }
    if (tid == 0) ((float*)(sm + O_BV2))[0] = p.bv2[0];
  }
  __syncthreads();

  const uint32_t smb  = smem_u32(sm);
  const uint32_t bufA = smb + OACTA;
  const uint32_t bufB = smb + OACTB;
  const uint32_t wE1  = smb + OW_E1;
  const uint32_t wV1  = smb + OW_V1;
  const uint32_t wE2  = smb + OW_E2;
  const uint32_t wE3  = smb + OW_E3;

  int*   sDst  = (int*)(sm + O_DST);
  int*   sSrc  = (int*)(sm + O_SRC);
  float* sRel  = (float*)(sm + O_REL);
  float* sFeat = (float*)(sm + O_FEAT);
  const float* w5e = (const float*)(sm + O_W5E);
  const float* w5v = (const float*)(sm + O_W5V);
  const float* cBE1 = (const float*)(sm + O_BE1);
  const float* cGE1 = (const float*)(sm + O_GE1);
  const float* cBT1 = (const float*)(sm + O_BTE1);
  const float* cBV1 = (const float*)(sm + O_BV1);
  const float* cGV1 = (const float*)(sm + O_GV1);
  const float* cBTV = (const float*)(sm + O_BTV1);
  const float* cWV2 = (const float*)(sm + O_WV2);
  const float* cBE2 = (const float*)(sm + O_BE2);
  const float* cBE3 = (const float*)(sm + O_BE3);

  const int g  = lane >> 2;
  const int q  = lane & 3;
  const int m0 = wid * 16;
  const int rA = m0 + g;
  const int rB = rA + 8;

  float acc[16][4];

#pragma unroll 1
  for (int tile = blockIdx.x; tile < NTILES; tile += gridDim.x) {
    __syncthreads();
    const int e0 = tile * ETILE;

    // ------------- geometry -------------
    if (tid < ETILE) {
      int e = e0 + tid;
      int s = p.ei[e], d = p.ei[NEDGES + e];
      sSrc[tid] = s;
      sDst[tid] = d;
      float2 ps = ((const float2*)p.pos)[s], pd = ((const float2*)p.pos)[d];
      float2 vs = ((const float2*)p.vel)[s], vd = ((const float2*)p.vel)[d];
      float rpx = ps.x - pd.x, rpy = ps.y - pd.y;
      float rvx = vs.x - vd.x, rvy = vs.y - vd.y;
      float dist = rpx * rpx + rpy * rpy;
      float dvr  = rvx * rpx + rvy * rpy;
      float r2   = fminf(1.f / (dist + 0.05f), 20.f);
      float r6   = fminf(r2 * r2 * r2, 400.f);
      float r12  = fminf(r6 * r6, 160000.f);
      sFeat[tid * 5 + 0] = dist;
      sFeat[tid * 5 + 1] = dvr;
      sFeat[tid * 5 + 2] = r2;
      sFeat[tid * 5 + 3] = r6;
      sFeat[tid * 5 + 4] = r12;
      sRel[2 * tid]     = rpx;
      sRel[2 * tid + 1] = rpy;
    }
    __syncthreads();

    // ------------- batched gather: 16 LDG.128 in flight per thread ---------
    {
      float4 vreg[16];
      int    eidx[16], col4[16];
#pragma unroll
      for (int u = 0; u < 16; ++u) {
        int i = tid + u * 256;
        int e = i >> 5, qq = i & 31;
        int half = qq >> 4, c4 = qq & 15;
        int node = half ? sSrc[e] : sDst[e];
        eidx[u] = e;
        col4[u] = half * 64 + c4 * 4;
        vreg[u] = ((const float4*)p.x)[node * 16 + c4];
      }
#pragma unroll
      for (int u = 0; u < 16; ++u) {
        uint2 pk;
        pk.x = h2pack(vreg[u].x, vreg[u].y);
        pk.y = h2pack(vreg[u].z, vreg[u].w);
        *(uint2*)(sm + OACTA + swb(eidx[u], col4[u])) = pk;
      }
    }
    __syncthreads();

    float fA[5], fB[5];
#pragma unroll
    for (int j = 0; j < 5; ++j) {
      fA[j] = sFeat[rA * 5 + j];
      fB[j] = sFeat[rB * 5 + j];
    }

    // ================= stage 1a: E1 = A @ We1 =================
    warp_gemm(bufA, wE1, m0, lane, acc);
    {
      float sa = 0.f, s2a = 0.f, sb = 0.f, s2b = 0.f;
#pragma unroll
      for (int f = 0; f < 16; ++f) {
#pragma unroll
        for (int t = 0; t < 2; ++t) {
          int c = 8 * f + 2 * q + t;
          float w0 = w5e[c], w1 = w5e[128 + c], w2 = w5e[256 + c],
                w3 = w5e[384 + c], w4 = w5e[512 + c];
          float bb = cBE1[c];
          float za = acc[f][t] + bb + fA[0] * w0 + fA[1] * w1 + fA[2] * w2 +
                     fA[3] * w3 + fA[4] * w4;
          float zb = acc[f][2 + t] + bb + fB[0] * w0 + fB[1] * w1 +
                     fB[2] * w2 + fB[3] * w3 + fB[4] * w4;
          acc[f][t] = za;
          acc[f][2 + t] = zb;
          sa += za; s2a = fmaf(za, za, s2a);
          sb += zb; s2b = fmaf(zb, zb, s2b);
        }
      }
#pragma unroll
      for (int m = 1; m < 4; m <<= 1) {
        sa  += __shfl_xor_sync(0xffffffffu, sa, m);
        s2a += __shfl_xor_sync(0xffffffffu, s2a, m);
        sb  += __shfl_xor_sync(0xffffffffu, sb, m);
        s2b += __shfl_xor_sync(0xffffffffu, s2b, m);
      }
      float mua = sa * (1.f / 128.f);
      float ria = rsqrtf(s2a * (1.f / 128.f) - mua * mua + 1e-5f);
      float mub = sb * (1.f / 128.f);
      float rib = rsqrtf(s2b * (1.f / 128.f) - mub * mub + 1e-5f);
#pragma unroll
      for (int f = 0; f < 16; ++f) {
        int c0 = 8 * f + 2 * q;
        float ha0 = softplus_f((acc[f][0] - mua) * ria * cGE1[c0] + cBT1[c0]);
        float ha1 = softplus_f((acc[f][1] - mua) * ria * cGE1[c0 + 1] + cBT1[c0 + 1]);
        float hb0 = softplus_f((acc[f][2] - mub) * rib * cGE1[c0] + cBT1[c0]);
        float hb1 = softplus_f((acc[f][3] - mub) * rib * cGE1[c0 + 1] + cBT1[c0 + 1]);
        *(uint32_t*)(sm + OACTB + swb(rA, c0)) = h2pack(ha0, ha1);
        *(uint32_t*)(sm + OACTB + swb(rB, c0)) = h2pack(hb0, hb1);
      }
    }

    // ================= stage 1b: V = A @ Wv1 =================
    warp_gemm(bufA, wV1, m0, lane, acc);
    {
      float sa = 0.f, s2a = 0.f, sb = 0.f, s2b = 0.f;
#pragma unroll
      for (int f = 0; f < 16; ++f) {
#pragma unroll
        for (int t = 0; t < 2; ++t) {
          int c = 8 * f + 2 * q + t;
          float w0 = w5v[c], w1 = w5v[128 + c], w2 = w5v[256 + c],
                w3 = w5v[384 + c], w4 = w5v[512 + c];
          float bb = cBV1[c];
          float za = acc[f][t] + bb + fA[0] * w0 + fA[1] * w1 + fA[2] * w2 +
                     fA[3] * w3 + fA[4] * w4;
          float zb = acc[f][2 + t] + bb + fB[0] * w0 + fB[1] * w1 +
                     fB[2] * w2 + fB[3] * w3 + fB[4] * w4;
          acc[f][t] = za;
          acc[f][2 + t] = zb;
          sa += za; s2a = fmaf(za, za, s2a);
          sb += zb; s2b = fmaf(zb, zb, s2b);
        }
      }
#pragma unroll
      for (int m = 1; m < 4; m <<= 1) {
        sa  += __shfl_xor_sync(0xffffffffu, sa, m);
        s2a += __shfl_xor_sync(0xffffffffu, s2a, m);
        sb  += __shfl_xor_sync(0xffffffffu, sb, m);
        s2b += __shfl_xor_sync(0xffffffffu, s2b, m);
      }
      float mua = sa * (1.f / 128.f);
      float ria = rsqrtf(s2a * (1.f / 128.f) - mua * mua + 1e-5f);
      float mub = sb * (1.f / 128.f);
      float rib = rsqrtf(s2b * (1.f / 128.f) - mub * mub + 1e-5f);
      float va = 0.f, vb = 0.f;
#pragma unroll
      for (int f = 0; f < 16; ++f) {
#pragma unroll
        for (int t = 0; t < 2; ++t) {
          int c = 8 * f + 2 * q + t;
          float gv = cGV1[c], bt = cBTV[c], wv = cWV2[c];
          va += softplus_f((acc[f][t] - mua) * ria * gv + bt) * wv;
          vb += softplus_f((acc[f][2 + t] - mub) * rib * gv + bt) * wv;
        }
      }
#pragma unroll
      for (int m = 1; m < 4; m <<= 1) {
        va += __shfl_xor_sync(0xffffffffu, va, m);
        vb += __shfl_xor_sync(0xffffffffu, vb, m);
      }
      if (q == 0) {
        float bv2v = ((const float*)(sm + O_BV2))[0];
        int dA = sDst[rA];
        float vwa = va + bv2v;
        red2(&g_mv[2 * dA], vwa * sRel[2 * rA], vwa * sRel[2 * rA + 1]);
        atomicAdd(&g_cnt[dA], 1.f);
        int dB = sDst[rB];
        float vwb = vb + bv2v;
        red2(&g_mv[2 * dB], vwb * sRel[2 * rB], vwb * sRel[2 * rB + 1]);
        atomicAdd(&g_cnt[dB], 1.f);
      }
    }

    // ================= stage 2: E2 = H1 @ We2 =================
    __syncwarp();
    warp_gemm(bufB, wE2, m0, lane, acc);
    {
#pragma unroll
      for (int f = 0; f < 16; ++f) {
        int c0 = 8 * f + 2 * q;
        float b0 = cBE2[c0], b1 = cBE2[c0 + 1];
        float ha0 = softplus_f(acc[f][0] + b0);
        float ha1 = softplus_f(acc[f][1] + b1);
        float hb0 = softplus_f(acc[f][2] + b0);
        float hb1 = softplus_f(acc[f][3] + b1);
        *(uint32_t*)(sm + OACTA + swb(rA, c0)) = h2pack(ha0, ha1);
        *(uint32_t*)(sm + OACTA + swb(rB, c0)) = h2pack(hb0, hb1);
      }
    }

    // ================= stage 3: E3 = H2 @ We3 -> vectorized scatter ========
    __syncwarp();
    warp_gemm(bufA, wE3, m0, lane, acc);
    {
      int dA = sDst[rA], dB = sDst[rB];
      float* gpa = g_mh + dA * H;
      float* gpb = g_mh + dB * H;
      const bool odd = (q & 1);
#pragma unroll
      for (int f = 0; f < 16; ++f) {
        int c0 = 8 * f + 2 * q;
        float b0 = cBE3[c0], b1 = cBE3[c0 + 1];
        float a0 = acc[f][0] + b0;   // row rA cols c0, c0+1
        float a1 = acc[f][1] + b1;
        float a2 = acc[f][2] + b0;   // row rB cols c0, c0+1
        float a3 = acc[f][3] + b1;
        // pair-exchange with lane q^1: even lane -> row rA 4 cols,
        // odd lane -> row rB 4 cols
        float u0 = __shfl_xor_sync(0xffffffffu, odd ? a0 : a2, 1);
        float u1 = __shfl_xor_sync(0xffffffffu, odd ? a1 : a3, 1);
        float* ptr = odd ? (gpb + c0 - 2) : (gpa + c0);
        float v0 = odd ? u0 : a0;
        float v1 = odd ? u1 : a1;
        float v2 = odd ? a2 : u0;
        float v3 = odd ? a3 : u1;
        red4(ptr, v0, v1, v2, v3);
      }
    }
  }
}

// ------------------------------ node kernel --------------------------------
template <int STRIDE, int KACT, int NCHUNK>
__device__ __forceinline__ void gemm_tile(const float* __restrict__ W,
                                          const float* sA_, float* sB_,
                                          float acc[8][8], int tx, int ty,
                                          int tid) {
  int wrow = tid >> 5, wc4 = tid & 31;
  float4 v;
  {
    int k = wrow;
    v = (k < KACT) ? reinterpret_cast<const float4*>(W)[k * 32 + wc4]
                   : make_float4(0.f, 0.f, 0.f, 0.f);
  }
#pragma unroll 1
  for (int ch = 0; ch < NCHUNK; ++ch) {
    reinterpret_cast<float4*>(sB_)[tid] = v;
    __syncthreads();
    if (ch + 1 < NCHUNK) {
      int k = (ch + 1) * 8 + wrow;
      v = (k < KACT) ? reinterpret_cast<const float4*>(W)[k * 32 + wc4]
                     : make_float4(0.f, 0.f, 0.f, 0.f);
    }
    int k0 = ch * 8;
#pragma unroll
    for (int kk = 0; kk < 8; ++kk) {
      float a[8];
#pragma unroll
      for (int r = 0; r < 8; ++r) a[r] = sA_[(ty * 8 + r) * STRIDE + k0 + kk];
      const float4* bp = reinterpret_cast<const float4*>(sB_ + kk * 128 + tx * 8);
      float4 b0 = bp[0], b1 = bp[1];
      float b[8] = {b0.x, b0.y, b0.z, b0.w, b1.x, b1.y, b1.z, b1.w};
#pragma unroll
      for (int r = 0; r < 8; ++r)
#pragma unroll
        for (int c = 0; c < 8; ++c) acc[r][c] = fmaf(a[r], b[c], acc[r][c]);
    }
    __syncthreads();
  }
}

__global__ void __launch_bounds__(256, 1) node_kernel(NodeParams p) {
  extern __shared__ float smem_dyn[];
  float* sA   = smem_dyn;
  float* sH   = sA + 128 * KHP;
  float* sB   = sH + 128 * H;
  float* sDen = sB + 8 * H;

  int tid = threadIdx.x;
  int tx = tid & 15, ty = tid >> 4;
  int n0 = blockIdx.x * 128;

  for (int i = tid; i < 128 * KHP; i += 256) sA[i] = 0.f;
  __syncthreads();
  if (tid < 128) {
    int n = n0 + tid;
    float den = 1.f, nrm = 0.f;
    if (n < NNODES) {
      den = fmaxf(g_cnt[n], 1.f);
      float mvx = g_mv[2 * n] / den + 1e-8f;
      float mvy = g_mv[2 * n + 1] / den + 1e-8f;
      nrm = sqrtf(mvx * mvx + mvy * mvy);
    }
    sDen[tid] = den;
    sA[tid * KHP + 192] = nrm;
  }
  __syncthreads();
  for (int i = tid; i < 128 * 64; i += 256) {
    int r = i >> 6, c = i & 63;
    int n = n0 + r;
    if (n < NNODES) sA[r * KHP + c] = p.x[n * 64 + c];
  }
  for (int i = tid; i < 128 * H; i += 256) {
    int r = i >> 7, c = i & 127;
    int n = n0 + r;
    if (n < NNODES) sA[r * KHP + 64 + c] = g_mh[n * 128 + c] / sDen[r];
  }
  __syncthreads();

  float acc[8][8];
#pragma unroll
  for (int r = 0; r < 8; ++r)
#pragma unroll
    for (int c = 0; c < 8; ++c) acc[r][c] = 0.f;
  gemm_tile<KHP, KH, 25>(p.Wh1, sA, sB, acc, tx, ty, tid);
  {
    float bias[8], g[8], bt[8];
#pragma unroll
    for (int c = 0; c < 8; ++c) {
      int col = tx * 8 + c;
      bias[c] = p.bh1[col]; g[c] = p.gh1[col]; bt[c] = p.bth1[col];
    }
#pragma unroll
    for (int r = 0; r < 8; ++r) {
      float z[8], s = 0.f, s2 = 0.f;
#pragma unroll
      for (int c = 0; c < 8; ++c) {
        z[c] = acc[r][c] + bias[c];
        s += z[c]; s2 += z[c] * z[c];
      }
#pragma unroll
      for (int m = 1; m < 16; m <<= 1) {
        s  += __shfl_xor_sync(0xffffffffu, s, m);
        s2 += __shfl_xor_sync(0xffffffffu, s2, m);
      }
      float mu = s * (1.f / 128.f);
      float var = s2 * (1.f / 128.f) - mu * mu;
      float rinv = rsqrtf(var + 1e-5f);
      int row = ty * 8 + r;
#pragma unroll
      for (int c = 0; c < 8; ++c)
        sH[row * H + tx * 8 + c] =
            softplus_f((z[c] - mu) * rinv * g[c] + bt[c]);
    }
  }
  __syncthreads();

  float acc2[8][4];
#pragma unroll
  for (int r = 0; r < 8; ++r)
#pragma unroll
    for (int c = 0; c < 4; ++c) acc2[r][c] = 0.f;
#pragma unroll 1
  for (int ch = 0; ch < 16; ++ch) {
    int k0 = ch * 8;
    if (tid < 128) {
      reinterpret_cast<float4*>(sB)[tid] =
          reinterpret_cast<const float4*>(p.Wh2)[(k0 + (tid >> 4)) * 16 +
                                                 (tid & 15)];
    }
    __syncthreads();
#pragma unroll
    for (int kk = 0; kk < 8; ++kk) {
      float a[8];
#pragma unroll
      for (int r = 0; r < 8; ++r) a[r] = sH[(ty * 8 + r) * H + k0 + kk];
      float4 b4 = reinterpret_cast<const float4*>(sB + kk * 64 + tx * 4)[0];
      float b[4] = {b4.x, b4.y, b4.z, b4.w};
#pragma unroll
      for (int r = 0; r < 8; ++r)
#pragma unroll
        for (int c = 0; c < 4; ++c) acc2[r][c] = fmaf(a[r], b[c], acc2[r][c]);
    }
    __syncthreads();
  }
  float bias2[4];
#pragma unroll
  for (int c = 0; c < 4; ++c) bias2[c] = p.bh2[tx * 4 + c];
#pragma unroll
  for (int r = 0; r < 8; ++r) {
    int n = n0 + ty * 8 + r;
    if (n < NNODES) {
#pragma unroll
      for (int c = 0; c < 4; ++c) {
        int col = tx * 4 + c;
        p.out[n * 64 + col] = p.x[n * 64 + col] + acc2[r][c] + bias2[c];
      }
    }
  }
}

// ------------------------------ launch -------------------------------------
extern "C" void kernel_launch(void* const* d_in, const int* in_sizes, int n_in,
                              void* d_out, int out_size) {
  EdgeParams ep;
  ep.x    = (const float*)d_in[0];
  ep.pos  = (const float*)d_in[1];
  ep.vel  = (const float*)d_in[2];
  ep.We1  = (const float*)d_in[3];
  ep.be1  = (const float*)d_in[4];
  ep.ge1  = (const float*)d_in[5];
  ep.bte1 = (const float*)d_in[6];
  ep.We2  = (const float*)d_in[7];
  ep.be2  = (const float*)d_in[8];
  ep.We3  = (const float*)d_in[9];
  ep.be3  = (const float*)d_in[10];
  ep.Wv1  = (const float*)d_in[11];
  ep.bv1  = (const float*)d_in[12];
  ep.gv1  = (const float*)d_in[13];
  ep.btv1 = (const float*)d_in[14];
  ep.Wv2  = (const float*)d_in[15];
  ep.bv2  = (const float*)d_in[16];
  ep.ei   = (const int*)d_in[23];

  NodeParams np;
  np.x    = ep.x;
  np.Wh1  = (const float*)d_in[17];
  np.bh1  = (const float*)d_in[18];
  np.gh1  = (const float*)d_in[19];
  np.bth1 = (const float*)d_in[20];
  np.Wh2  = (const float*)d_in[21];
  np.bh2  = (const float*)d_in[22];
  np.out  = (float*)d_out;

  int node_smem = (128 * KHP + 128 * H + 8 * H + 128) * (int)sizeof(float);
  cudaFuncSetAttribute(edge_kernel, cudaFuncAttributeMaxDynamicSharedMemorySize,
                       EDGE_SMEM);
  cudaFuncSetAttribute(node_kernel, cudaFuncAttributeMaxDynamicSharedMemorySize,
                       node_smem);

  zero_kernel<<<(NNODES * H + 255) / 256, 256>>>();
  edge_kernel<<<148, 256, EDGE_SMEM>>>(ep);
  node_kernel<<<(NNODES + 127) / 128, 256, node_smem>>>(np);
}

// round 7
// speedup vs baseline: 5.3714x; 1.0482x over previous
#include <cuda_runtime.h>
#include <cuda_fp16.h>
#include <cstdint>

// ---------------------------------------------------------------------------
// R6: R5 + features folded into the MMA (K=144 for E1/V GEMMs).
//   - Geometric features stored as fp16 in a 128x16 A-extension tile
//     (r12 scaled by 2^-2; matching weight row scaled by 2^2 -> product exact
//     up to fp16 rounding, no overflow). Rank-5 fp32 epilogue removed.
//   - E1/V weight tiles get a 16-row K-extension (rows 128..132 + zeros).
//   - red.v4/v2 scatter + batched gather retained from R5.
// ---------------------------------------------------------------------------

namespace {
constexpr int NNODES = 20000;
constexpr int NEDGES = 640000;
constexpr int H      = 128;
constexpr int ETILE  = 128;
constexpr int NTILES = NEDGES / ETILE;   // 5000
constexpr int KH     = 193;
constexpr int KHP    = 200;

constexpr int OW_E1  = 0;        // 32 KB each
constexpr int OW_V1  = 32768;
constexpr int OW_E2  = 65536;
constexpr int OW_E3  = 98304;
constexpr int OWX_E1 = 131072;   // 16x128 fp16 ext (4 KB)
constexpr int OWX_V1 = 135168;   // 4 KB
constexpr int OACTA  = 139264;   // 32 KB
constexpr int OACTX  = 172032;   // A-ext: 128 rows x 48 B (6 KB)
constexpr int OACTB  = 178176;   // 32 KB
constexpr int O_BE1  = 210944;
constexpr int O_GE1  = 211456;
constexpr int O_BTE1 = 211968;
constexpr int O_BV1  = 212480;
constexpr int O_GV1  = 212992;
constexpr int O_BTV1 = 213504;
constexpr int O_WV2  = 214016;
constexpr int O_BE2  = 214528;
constexpr int O_BE3  = 215040;
constexpr int O_REL  = 215552;   // 128*2 fp32
constexpr int O_DST  = 216576;   // 128 int
constexpr int O_SRC  = 217088;   // 128 int
constexpr int O_BV2  = 217600;
constexpr int EDGE_SMEM = 217728;
}  // namespace

__device__ __align__(16) float g_mh[NNODES * H];
__device__ __align__(16) float g_mv[NNODES * 2];
__device__ float g_cnt[NNODES];

struct EdgeParams {
  const float *x, *pos, *vel;
  const float *We1, *be1, *ge1, *bte1, *We2, *be2, *We3, *be3;
  const float *Wv1, *bv1, *gv1, *btv1, *Wv2, *bv2;
  const int   *ei;
};
struct NodeParams {
  const float *x;
  const float *Wh1, *bh1, *gh1, *bth1, *Wh2, *bh2;
  float       *out;
};

// ------------------------------- helpers -----------------------------------
__device__ __forceinline__ uint32_t smem_u32(const void* p) {
  uint32_t a;
  asm("{ .reg .u64 t; cvta.to.shared.u64 t, %1; cvt.u32.u64 %0, t; }"
      : "=r"(a) : "l"(p));
  return a;
}
__device__ __forceinline__ void ldsm4(uint32_t& a0, uint32_t& a1, uint32_t& a2,
                                      uint32_t& a3, uint32_t addr) {
  asm volatile(
      "ldmatrix.sync.aligned.m8n8.x4.shared.b16 {%0,%1,%2,%3}, [%4];"
      : "=r"(a0), "=r"(a1), "=r"(a2), "=r"(a3) : "r"(addr));
}
__device__ __forceinline__ void ldsm4t(uint32_t& a0, uint32_t& a1, uint32_t& a2,
                                       uint32_t& a3, uint32_t addr) {
  asm volatile(
      "ldmatrix.sync.aligned.m8n8.x4.trans.shared.b16 {%0,%1,%2,%3}, [%4];"
      : "=r"(a0), "=r"(a1), "=r"(a2), "=r"(a3) : "r"(addr));
}
__device__ __forceinline__ void mma16816(float* c, uint32_t a0, uint32_t a1,
                                         uint32_t a2, uint32_t a3, uint32_t b0,
                                         uint32_t b1) {
  asm volatile(
      "mma.sync.aligned.m16n8k16.row.col.f32.f16.f16.f32 "
      "{%0,%1,%2,%3}, {%4,%5,%6,%7}, {%8,%9}, {%0,%1,%2,%3};"
      : "+f"(c[0]), "+f"(c[1]), "+f"(c[2]), "+f"(c[3])
      : "r"(a0), "r"(a1), "r"(a2), "r"(a3), "r"(b0), "r"(b1));
}
__device__ __forceinline__ void red4(float* p, float a, float b, float c,
                                     float d) {
  asm volatile("red.global.add.v4.f32 [%0], {%1,%2,%3,%4};"
               :: "l"(p), "f"(a), "f"(b), "f"(c), "f"(d) : "memory");
}
__device__ __forceinline__ void red2(float* p, float a, float b) {
  asm volatile("red.global.add.v2.f32 [%0], {%1,%2};"
               :: "l"(p), "f"(a), "f"(b) : "memory");
}
// byte offset in a 128x128 fp16 tile: 256B rows, 16B-chunk xor swizzle
__device__ __forceinline__ uint32_t swb(int row, int col) {
  return (uint32_t)row * 256u + (uint32_t)((((col >> 3) ^ (row & 7)) & 15) << 4) +
         (uint32_t)((col & 7) << 1);
}
__device__ __forceinline__ uint32_t h2pack(float a, float b) {
  __half2 h = __floats2half2_rn(a, b);
  return (uint32_t)__half_as_ushort(__low2half(h)) |
         ((uint32_t)__half_as_ushort(__high2half(h)) << 16);
}
__device__ __forceinline__ float softplus_f(float v) {
  return fmaxf(v, 0.f) + __logf(1.f + __expf(-fabsf(v)));
}

// acc[16][4] = rows [m0..m0+15] of (Atile @ Wtile); K=128, plus optional
// K-extension step (k=128..143) reading A-ext (48B rows) and W-ext tiles.
template <bool EXT>
__device__ __forceinline__ void warp_gemm(uint32_t smA, uint32_t smW,
                                          uint32_t smAx, uint32_t smWx,
                                          int m0, int lane, float acc[16][4]) {
#pragma unroll
  for (int f = 0; f < 16; ++f)
#pragma unroll
    for (int e = 0; e < 4; ++e) acc[f][e] = 0.f;

  const int mid = lane >> 3;
  const int wi  = lane & 7;
  const int arow = m0 + wi + (mid & 1) * 8;
  const uint32_t arow_base = smA + (uint32_t)arow * 256u;
  const int ar7 = arow & 7;

#pragma unroll
  for (int k = 0; k < 8; ++k) {
    const int k0 = k * 16;
    int cha = (k0 >> 3) + (mid >> 1);
    uint32_t a0, a1, a2, a3;
    ldsm4(a0, a1, a2, a3, arow_base + (uint32_t)(((cha ^ ar7) & 15) << 4));
    const int krow = k0 + wi + (mid & 1) * 8;
    const uint32_t brow_base = smW + (uint32_t)krow * 256u;
    const int kr7 = krow & 7;
#pragma unroll
    for (int nf2 = 0; nf2 < 8; ++nf2) {
      int chb = (nf2 << 1) + (mid >> 1);
      uint32_t b0, b1, b2, b3;
      ldsm4t(b0, b1, b2, b3, brow_base + (uint32_t)(((chb ^ kr7) & 15) << 4));
      mma16816(acc[2 * nf2],     a0, a1, a2, a3, b0, b1);
      mma16816(acc[2 * nf2 + 1], a0, a1, a2, a3, b2, b3);
    }
  }
  if (EXT) {
    // k-step 8: k = 128..143 (features + zero pad)
    uint32_t a0, a1, a2, a3;
    ldsm4(a0, a1, a2, a3,
          smAx + (uint32_t)arow * 48u + (uint32_t)((mid >> 1) << 4));
    const int krowe = wi + (mid & 1) * 8;
    const uint32_t brow_base = smWx + (uint32_t)krowe * 256u;
    const int kr7e = krowe & 7;
#pragma unroll
    for (int nf2 = 0; nf2 < 8; ++nf2) {
      int chb = (nf2 << 1) + (mid >> 1);
      uint32_t b0, b1, b2, b3;
      ldsm4t(b0, b1, b2, b3, brow_base + (uint32_t)(((chb ^ kr7e) & 15) << 4));
      mma16816(acc[2 * nf2],     a0, a1, a2, a3, b0, b1);
      mma16816(acc[2 * nf2 + 1], a0, a1, a2, a3, b2, b3);
    }
  }
}

__global__ void zero_kernel() {
  int i = blockIdx.x * 256 + threadIdx.x;
  if (i < NNODES * H) g_mh[i] = 0.f;
  if (i < NNODES * 2) g_mv[i] = 0.f;
  if (i < NNODES)     g_cnt[i] = 0.f;
}

// ------------------------------ edge kernel --------------------------------
__global__ void __launch_bounds__(256, 1) edge_kernel(EdgeParams p) {
  extern __shared__ __align__(1024) char sm[];
  const int tid  = threadIdx.x;
  const int wid  = tid >> 5;
  const int lane = tid & 31;

  // ---------------- prologue: weights / params into smem -----------------
  {
    const float* Wm[4] = {p.We1, p.Wv1, p.We2, p.We3};
#pragma unroll 1
    for (int m = 0; m < 4; ++m) {
      const float* W = Wm[m];
      char* base = sm + m * 32768;
      for (int i = tid; i < 4096; i += 256) {
        int k  = i >> 5;
        int c4 = (i & 31) << 2;
        float4 w = *(const float4*)(W + k * 128 + c4);
        uint2 pk;
        pk.x = h2pack(w.x, w.y);
        pk.y = h2pack(w.z, w.w);
        *(uint2*)(base + swb(k, c4)) = pk;
      }
    }
    // K-extension tiles for We1/Wv1: rows 0..4 = W rows 128..132
    // (row 4 = r12 row scaled by 4; feature stores r12*0.25), rows 5..15 = 0.
    const float* Wx[2] = {p.We1, p.Wv1};
    const int    Ox[2] = {OWX_E1, OWX_V1};
#pragma unroll 1
    for (int m = 0; m < 2; ++m) {
      const float* W = Wx[m];
      char* base = sm + Ox[m];
      for (int i = tid; i < 512; i += 256) {   // 16 rows x 32 col-groups
        int row = i >> 5;
        int c4  = (i & 31) << 2;
        float sc = (row == 4) ? 4.f : 1.f;
        float w0 = 0.f, w1 = 0.f, w2 = 0.f, w3 = 0.f;
        if (row < 5) {
          const float* wr = W + (128 + row) * 128 + c4;
          w0 = wr[0] * sc; w1 = wr[1] * sc; w2 = wr[2] * sc; w3 = wr[3] * sc;
        }
        uint2 pk;
        pk.x = h2pack(w0, w1);
        pk.y = h2pack(w2, w3);
        *(uint2*)(base + swb(row, c4)) = pk;
      }
    }
    if (tid < 128) {
      ((float*)(sm + O_BE1))[tid]  = p.be1[tid];
      ((float*)(sm + O_GE1))[tid]  = p.ge1[tid];
      ((float*)(sm + O_BTE1))[tid] = p.bte1[tid];
      ((float*)(sm + O_BV1))[tid]  = p.bv1[tid];
      ((float*)(sm + O_GV1))[tid]  = p.gv1[tid];
      ((float*)(sm + O_BTV1))[tid] = p.btv1[tid];
      ((float*)(sm + O_WV2))[tid]  = p.Wv2[tid];
      ((float*)(sm + O_BE2))[tid]  = p.be2[tid];
      ((float*)(sm + O_BE3))[tid]  = p.be3[tid];
    }
    if (tid == 0) ((float*)(sm + O_BV2))[0] = p.bv2[0];
  }
  __syncthreads();

  const uint32_t smb  = smem_u32(sm);
  const uint32_t bufA = smb + OACTA;
  const uint32_t bufAx= smb + OACTX;
  const uint32_t bufB = smb + OACTB;
  const uint32_t wE1  = smb + OW_E1;
  const uint32_t wV1  = smb + OW_V1;
  const uint32_t wE2  = smb + OW_E2;
  const uint32_t wE3  = smb + OW_E3;
  const uint32_t wxE1 = smb + OWX_E1;
  const uint32_t wxV1 = smb + OWX_V1;

  int*   sDst = (int*)(sm + O_DST);
  int*   sSrc = (int*)(sm + O_SRC);
  float* sRel = (float*)(sm + O_REL);
  const float* cBE1 = (const float*)(sm + O_BE1);
  const float* cGE1 = (const float*)(sm + O_GE1);
  const float* cBT1 = (const float*)(sm + O_BTE1);
  const float* cBV1 = (const float*)(sm + O_BV1);
  const float* cGV1 = (const float*)(sm + O_GV1);
  const float* cBTV = (const float*)(sm + O_BTV1);
  const float* cWV2 = (const float*)(sm + O_WV2);
  const float* cBE2 = (const float*)(sm + O_BE2);
  const float* cBE3 = (const float*)(sm + O_BE3);

  const int g  = lane >> 2;
  const int q  = lane & 3;
  const int m0 = wid * 16;
  const int rA = m0 + g;
  const int rB = rA + 8;

  float acc[16][4];

#pragma unroll 1
  for (int tile = blockIdx.x; tile < NTILES; tile += gridDim.x) {
    __syncthreads();
    const int e0 = tile * ETILE;

    // ------------- geometry: fp16 features straight into A-ext -------------
    if (tid < ETILE) {
      int e = e0 + tid;
      int s = p.ei[e], d = p.ei[NEDGES + e];
      sSrc[tid] = s;
      sDst[tid] = d;
      float2 ps = ((const float2*)p.pos)[s], pd = ((const float2*)p.pos)[d];
      float2 vs = ((const float2*)p.vel)[s], vd = ((const float2*)p.vel)[d];
      float rpx = ps.x - pd.x, rpy = ps.y - pd.y;
      float rvx = vs.x - vd.x, rvy = vs.y - vd.y;
      float dist = rpx * rpx + rpy * rpy;
      float dvr  = rvx * rpx + rvy * rpy;
      float r2   = fminf(1.f / (dist + 0.05f), 20.f);
      float r6   = fminf(r2 * r2 * r2, 400.f);
      float r12  = fminf(r6 * r6, 160000.f);
      uint4 lo;
      lo.x = h2pack(dist, dvr);
      lo.y = h2pack(r2, r6);
      lo.z = h2pack(r12 * 0.25f, 0.f);
      lo.w = 0u;
      *(uint4*)(sm + OACTX + tid * 48)      = lo;
      *(uint4*)(sm + OACTX + tid * 48 + 16) = make_uint4(0u, 0u, 0u, 0u);
      sRel[2 * tid]     = rpx;
      sRel[2 * tid + 1] = rpy;
    }
    __syncthreads();

    // ------------- batched gather: 16 LDG.128 in flight per thread ---------
    {
      float4 vreg[16];
      int    eidx[16], col4[16];
#pragma unroll
      for (int u = 0; u < 16; ++u) {
        int i = tid + u * 256;
        int e = i >> 5, qq = i & 31;
        int half = qq >> 4, c4 = qq & 15;
        int node = half ? sSrc[e] : sDst[e];
        eidx[u] = e;
        col4[u] = half * 64 + c4 * 4;
        vreg[u] = ((const float4*)p.x)[node * 16 + c4];
      }
#pragma unroll
      for (int u = 0; u < 16; ++u) {
        uint2 pk;
        pk.x = h2pack(vreg[u].x, vreg[u].y);
        pk.y = h2pack(vreg[u].z, vreg[u].w);
        *(uint2*)(sm + OACTA + swb(eidx[u], col4[u])) = pk;
      }
    }
    __syncthreads();

    // ================= stage 1a: E1 = [A|feat] @ We1 (K=144) ===============
    warp_gemm<true>(bufA, wE1, bufAx, wxE1, m0, lane, acc);
    {
      float sa = 0.f, s2a = 0.f, sb = 0.f, s2b = 0.f;
#pragma unroll
      for (int f = 0; f < 16; ++f) {
#pragma unroll
        for (int t = 0; t < 2; ++t) {
          int c = 8 * f + 2 * q + t;
          float bb = cBE1[c];
          float za = acc[f][t] + bb;
          float zb = acc[f][2 + t] + bb;
          acc[f][t] = za;
          acc[f][2 + t] = zb;
          sa += za; s2a = fmaf(za, za, s2a);
          sb += zb; s2b = fmaf(zb, zb, s2b);
        }
      }
#pragma unroll
      for (int m = 1; m < 4; m <<= 1) {
        sa  += __shfl_xor_sync(0xffffffffu, sa, m);
        s2a += __shfl_xor_sync(0xffffffffu, s2a, m);
        sb  += __shfl_xor_sync(0xffffffffu, sb, m);
        s2b += __shfl_xor_sync(0xffffffffu, s2b, m);
      }
      float mua = sa * (1.f / 128.f);
      float ria = rsqrtf(s2a * (1.f / 128.f) - mua * mua + 1e-5f);
      float mub = sb * (1.f / 128.f);
      float rib = rsqrtf(s2b * (1.f / 128.f) - mub * mub + 1e-5f);
#pragma unroll
      for (int f = 0; f < 16; ++f) {
        int c0 = 8 * f + 2 * q;
        float ha0 = softplus_f((acc[f][0] - mua) * ria * cGE1[c0] + cBT1[c0]);
        float ha1 = softplus_f((acc[f][1] - mua) * ria * cGE1[c0 + 1] + cBT1[c0 + 1]);
        float hb0 = softplus_f((acc[f][2] - mub) * rib * cGE1[c0] + cBT1[c0]);
        float hb1 = softplus_f((acc[f][3] - mub) * rib * cGE1[c0 + 1] + cBT1[c0 + 1]);
        *(uint32_t*)(sm + OACTB + swb(rA, c0)) = h2pack(ha0, ha1);
        *(uint32_t*)(sm + OACTB + swb(rB, c0)) = h2pack(hb0, hb1);
      }
    }

    // ================= stage 1b: V = [A|feat] @ Wv1 (K=144) ================
    warp_gemm<true>(bufA, wV1, bufAx, wxV1, m0, lane, acc);
    {
      float sa = 0.f, s2a = 0.f, sb = 0.f, s2b = 0.f;
#pragma unroll
      for (int f = 0; f < 16; ++f) {
#pragma unroll
        for (int t = 0; t < 2; ++t) {
          int c = 8 * f + 2 * q + t;
          float bb = cBV1[c];
          float za = acc[f][t] + bb;
          float zb = acc[f][2 + t] + bb;
          acc[f][t] = za;
          acc[f][2 + t] = zb;
          sa += za; s2a = fmaf(za, za, s2a);
          sb += zb; s2b = fmaf(zb, zb, s2b);
        }
      }
#pragma unroll
      for (int m = 1; m < 4; m <<= 1) {
        sa  += __shfl_xor_sync(0xffffffffu, sa, m);
        s2a += __shfl_xor_sync(0xffffffffu, s2a, m);
        sb  += __shfl_xor_sync(0xffffffffu, sb, m);
        s2b += __shfl_xor_sync(0xffffffffu, s2b, m);
      }
      float mua = sa * (1.f / 128.f);
      float ria = rsqrtf(s2a * (1.f / 128.f) - mua * mua + 1e-5f);
      float mub = sb * (1.f / 128.f);
      float rib = rsqrtf(s2b * (1.f / 128.f) - mub * mub + 1e-5f);
      float va = 0.f, vb = 0.f;
#pragma unroll
      for (int f = 0; f < 16; ++f) {
#pragma unroll
        for (int t = 0; t < 2; ++t) {
          int c = 8 * f + 2 * q + t;
          float gv = cGV1[c], bt = cBTV[c], wv = cWV2[c];
          va += softplus_f((acc[f][t] - mua) * ria * gv + bt) * wv;
          vb += softplus_f((acc[f][2 + t] - mub) * rib * gv + bt) * wv;
        }
      }
#pragma unroll
      for (int m = 1; m < 4; m <<= 1) {
        va += __shfl_xor_sync(0xffffffffu, va, m);
        vb += __shfl_xor_sync(0xffffffffu, vb, m);
      }
      if (q == 0) {
        float bv2v = ((const float*)(sm + O_BV2))[0];
        int dA = sDst[rA];
        float vwa = va + bv2v;
        red2(&g_mv[2 * dA], vwa * sRel[2 * rA], vwa * sRel[2 * rA + 1]);
        atomicAdd(&g_cnt[dA], 1.f);
        int dB = sDst[rB];
        float vwb = vb + bv2v;
        red2(&g_mv[2 * dB], vwb * sRel[2 * rB], vwb * sRel[2 * rB + 1]);
        atomicAdd(&g_cnt[dB], 1.f);
      }
    }

    // ================= stage 2: E2 = H1 @ We2 =================
    __syncwarp();
    warp_gemm<false>(bufB, wE2, 0, 0, m0, lane, acc);
    {
#pragma unroll
      for (int f = 0; f < 16; ++f) {
        int c0 = 8 * f + 2 * q;
        float b0 = cBE2[c0], b1 = cBE2[c0 + 1];
        float ha0 = softplus_f(acc[f][0] + b0);
        float ha1 = softplus_f(acc[f][1] + b1);
        float hb0 = softplus_f(acc[f][2] + b0);
        float hb1 = softplus_f(acc[f][3] + b1);
        *(uint32_t*)(sm + OACTA + swb(rA, c0)) = h2pack(ha0, ha1);
        *(uint32_t*)(sm + OACTA + swb(rB, c0)) = h2pack(hb0, hb1);
      }
    }

    // ================= stage 3: E3 = H2 @ We3 -> vectorized scatter ========
    __syncwarp();
    warp_gemm<false>(bufA, wE3, 0, 0, m0, lane, acc);
    {
      int dA = sDst[rA], dB = sDst[rB];
      float* gpa = g_mh + dA * H;
      float* gpb = g_mh + dB * H;
      const bool odd = (q & 1);
#pragma unroll
      for (int f = 0; f < 16; ++f) {
        int c0 = 8 * f + 2 * q;
        float b0 = cBE3[c0], b1 = cBE3[c0 + 1];
        float a0 = acc[f][0] + b0;
        float a1 = acc[f][1] + b1;
        float a2 = acc[f][2] + b0;
        float a3 = acc[f][3] + b1;
        float u0 = __shfl_xor_sync(0xffffffffu, odd ? a0 : a2, 1);
        float u1 = __shfl_xor_sync(0xffffffffu, odd ? a1 : a3, 1);
        float* ptr = odd ? (gpb + c0 - 2) : (gpa + c0);
        float v0 = odd ? u0 : a0;
        float v1 = odd ? u1 : a1;
        float v2 = odd ? a2 : u0;
        float v3 = odd ? a3 : u1;
        red4(ptr, v0, v1, v2, v3);
      }
    }
  }
}

// ------------------------------ node kernel --------------------------------
template <int STRIDE, int KACT, int NCHUNK>
__device__ __forceinline__ void gemm_tile(const float* __restrict__ W,
                                          const float* sA_, float* sB_,
                                          float acc[8][8], int tx, int ty,
                                          int tid) {
  int wrow = tid >> 5, wc4 = tid & 31;
  float4 v;
  {
    int k = wrow;
    v = (k < KACT) ? reinterpret_cast<const float4*>(W)[k * 32 + wc4]
                   : make_float4(0.f, 0.f, 0.f, 0.f);
  }
#pragma unroll 1
  for (int ch = 0; ch < NCHUNK; ++ch) {
    reinterpret_cast<float4*>(sB_)[tid] = v;
    __syncthreads();
    if (ch + 1 < NCHUNK) {
      int k = (ch + 1) * 8 + wrow;
      v = (k < KACT) ? reinterpret_cast<const float4*>(W)[k * 32 + wc4]
                     : make_float4(0.f, 0.f, 0.f, 0.f);
    }
    int k0 = ch * 8;
#pragma unroll
    for (int kk = 0; kk < 8; ++kk) {
      float a[8];
#pragma unroll
      for (int r = 0; r < 8; ++r) a[r] = sA_[(ty * 8 + r) * STRIDE + k0 + kk];
      const float4* bp = reinterpret_cast<const float4*>(sB_ + kk * 128 + tx * 8);
      float4 b0 = bp[0], b1 = bp[1];
      float b[8] = {b0.x, b0.y, b0.z, b0.w, b1.x, b1.y, b1.z, b1.w};
#pragma unroll
      for (int r = 0; r < 8; ++r)
#pragma unroll
        for (int c = 0; c < 8; ++c) acc[r][c] = fmaf(a[r], b[c], acc[r][c]);
    }
    __syncthreads();
  }
}

__global__ void __launch_bounds__(256, 1) node_kernel(NodeParams p) {
  extern __shared__ float smem_dyn[];
  float* sA   = smem_dyn;
  float* sH   = sA + 128 * KHP;
  float* sB   = sH + 128 * H;
  float* sDen = sB + 8 * H;

  int tid = threadIdx.x;
  int tx = tid & 15, ty = tid >> 4;
  int n0 = blockIdx.x * 128;

  for (int i = tid; i < 128 * KHP; i += 256) sA[i] = 0.f;
  __syncthreads();
  if (tid < 128) {
    int n = n0 + tid;
    float den = 1.f, nrm = 0.f;
    if (n < NNODES) {
      den = fmaxf(g_cnt[n], 1.f);
      float mvx = g_mv[2 * n] / den + 1e-8f;
      float mvy = g_mv[2 * n + 1] / den + 1e-8f;
      nrm = sqrtf(mvx * mvx + mvy * mvy);
    }
    sDen[tid] = den;
    sA[tid * KHP + 192] = nrm;
  }
  __syncthreads();
  for (int i = tid; i < 128 * 64; i += 256) {
    int r = i >> 6, c = i & 63;
    int n = n0 + r;
    if (n < NNODES) sA[r * KHP + c] = p.x[n * 64 + c];
  }
  for (int i = tid; i < 128 * H; i += 256) {
    int r = i >> 7, c = i & 127;
    int n = n0 + r;
    if (n < NNODES) sA[r * KHP + 64 + c] = g_mh[n * 128 + c] / sDen[r];
  }
  __syncthreads();

  float acc[8][8];
#pragma unroll
  for (int r = 0; r < 8; ++r)
#pragma unroll
    for (int c = 0; c < 8; ++c) acc[r][c] = 0.f;
  gemm_tile<KHP, KH, 25>(p.Wh1, sA, sB, acc, tx, ty, tid);
  {
    float bias[8], g[8], bt[8];
#pragma unroll
    for (int c = 0; c < 8; ++c) {
      int col = tx * 8 + c;
      bias[c] = p.bh1[col]; g[c] = p.gh1[col]; bt[c] = p.bth1[col];
    }
#pragma unroll
    for (int r = 0; r < 8; ++r) {
      float z[8], s = 0.f, s2 = 0.f;
#pragma unroll
      for (int c = 0; c < 8; ++c) {
        z[c] = acc[r][c] + bias[c];
        s += z[c]; s2 += z[c] * z[c];
      }
#pragma unroll
      for (int m = 1; m < 16; m <<= 1) {
        s  += __shfl_xor_sync(0xffffffffu, s, m);
        s2 += __shfl_xor_sync(0xffffffffu, s2, m);
      }
      float mu = s * (1.f / 128.f);
      float var = s2 * (1.f / 128.f) - mu * mu;
      float rinv = rsqrtf(var + 1e-5f);
      int row = ty * 8 + r;
#pragma unroll
      for (int c = 0; c < 8; ++c)
        sH[row * H + tx * 8 + c] =
            softplus_f((z[c] - mu) * rinv * g[c] + bt[c]);
    }
  }
  __syncthreads();

  float acc2[8][4];
#pragma unroll
  for (int r = 0; r < 8; ++r)
#pragma unroll
    for (int c = 0; c < 4; ++c) acc2[r][c] = 0.f;
#pragma unroll 1
  for (int ch = 0; ch < 16; ++ch) {
    int k0 = ch * 8;
    if (tid < 128) {
      reinterpret_cast<float4*>(sB)[tid] =
          reinterpret_cast<const float4*>(p.Wh2)[(k0 + (tid >> 4)) * 16 +
                                                 (tid & 15)];
    }
    __syncthreads();
#pragma unroll
    for (int kk = 0; kk < 8; ++kk) {
      float a[8];
#pragma unroll
      for (int r = 0; r < 8; ++r) a[r] = sH[(ty * 8 + r) * H + k0 + kk];
      float4 b4 = reinterpret_cast<const float4*>(sB + kk * 64 + tx * 4)[0];
      float b[4] = {b4.x, b4.y, b4.z, b4.w};
#pragma unroll
      for (int r = 0; r < 8; ++r)
#pragma unroll
        for (int c = 0; c < 4; ++c) acc2[r][c] = fmaf(a[r], b[c], acc2[r][c]);
    }
    __syncthreads();
  }
  float bias2[4];
#pragma unroll
  for (int c = 0; c < 4; ++c) bias2[c] = p.bh2[tx * 4 + c];
#pragma unroll
  for (int r = 0; r < 8; ++r) {
    int n = n0 + ty * 8 + r;
    if (n < NNODES) {
#pragma unroll
      for (int c = 0; c < 4; ++c) {
        int col = tx * 4 + c;
        p.out[n * 64 + col] = p.x[n * 64 + col] + acc2[r][c] + bias2[c];
      }
    }
  }
}

// ------------------------------ launch -------------------------------------
extern "C" void kernel_launch(void* const* d_in, const int* in_sizes, int n_in,
                              void* d_out, int out_size) {
  EdgeParams ep;
  ep.x    = (const float*)d_in[0];
  ep.pos  = (const float*)d_in[1];
  ep.vel  = (const float*)d_in[2];
  ep.We1  = (const float*)d_in[3];
  ep.be1  = (const float*)d_in[4];
  ep.ge1  = (const float*)d_in[5];
  ep.bte1 = (const float*)d_in[6];
  ep.We2  = (const float*)d_in[7];
  ep.be2  = (const float*)d_in[8];
  ep.We3  = (const float*)d_in[9];
  ep.be3  = (const float*)d_in[10];
  ep.Wv1  = (const float*)d_in[11];
  ep.bv1  = (const float*)d_in[12];
  ep.gv1  = (const float*)d_in[13];
  ep.btv1 = (const float*)d_in[14];
  ep.Wv2  = (const float*)d_in[15];
  ep.bv2  = (const float*)d_in[16];
  ep.ei   = (const int*)d_in[23];

  NodeParams np;
  np.x    = ep.x;
  np.Wh1  = (const float*)d_in[17];
  np.bh1  = (const float*)d_in[18];
  np.gh1  = (const float*)d_in[19];
  np.bth1 = (const float*)d_in[20];
  np.Wh2  = (const float*)d_in[21];
  np.bh2  = (const float*)d_in[22];
  np.out  = (float*)d_out;

  int node_smem = (128 * KHP + 128 * H + 8 * H + 128) * (int)sizeof(float);
  cudaFuncSetAttribute(edge_kernel, cudaFuncAttributeMaxDynamicSharedMemorySize,
                       EDGE_SMEM);
  cudaFuncSetAttribute(node_kernel, cudaFuncAttributeMaxDynamicSharedMemorySize,
                       node_smem);

  zero_kernel<<<(NNODES * H + 255) / 256, 256>>>();
  edge_kernel<<<148, 256, EDGE_SMEM>>>(ep);
  node_kernel<<<(NNODES + 127) / 128, 256, node_smem>>>(np);
}

// round 9
// speedup vs baseline: 6.0333x; 1.1232x over previous
#include <cuda_runtime.h>
#include <cuda_fp16.h>
#include <cstdint>

// ---------------------------------------------------------------------------
// R7: ETILE=256, 512 threads (16 warps -> 4/SMSP interleave), single in-place
//     activation buffer (V before E1; H1/H2 overwrite A per-warp), 2 block
//     barriers per tile, gather indices straight from ei (no sSrc).
//     Features stay folded into K=144 MMA (R6). red.v4/v2 scatter (R5).
// ---------------------------------------------------------------------------

namespace {
constexpr int NNODES = 20000;
constexpr int NEDGES = 640000;
constexpr int H      = 128;
constexpr int ETILE  = 256;
constexpr int NTILES = NEDGES / ETILE;   // 2500
constexpr int KH     = 193;
constexpr int KHP    = 200;

constexpr int OW_E1  = 0;        // 32 KB each (128 rows x 256 B)
constexpr int OW_V1  = 32768;
constexpr int OW_E2  = 65536;
constexpr int OW_E3  = 98304;
constexpr int OWX_E1 = 131072;   // 16x128 fp16 ext (4 KB)
constexpr int OWX_V1 = 135168;
constexpr int OACTA  = 139264;   // 256 rows x 256 B = 64 KB
constexpr int OACTX  = 204800;   // A-ext: 256 rows x 48 B = 12 KB
constexpr int O_BE1  = 217088;
constexpr int O_GE1  = 217600;
constexpr int O_BTE1 = 218112;
constexpr int O_BV1  = 218624;
constexpr int O_GV1  = 219136;
constexpr int O_BTV1 = 219648;
constexpr int O_WV2  = 220160;
constexpr int O_BE2  = 220672;
constexpr int O_BE3  = 221184;
constexpr int O_REL  = 221696;   // 256*2 fp32 = 2 KB
constexpr int O_DST  = 223744;   // 256 int = 1 KB
constexpr int O_BV2  = 224768;
constexpr int EDGE_SMEM = 224896;
}  // namespace

__device__ __align__(16) float g_mh[NNODES * H];
__device__ __align__(16) float g_mv[NNODES * 2];
__device__ float g_cnt[NNODES];

struct EdgeParams {
  const float *x, *pos, *vel;
  const float *We1, *be1, *ge1, *bte1, *We2, *be2, *We3, *be3;
  const float *Wv1, *bv1, *gv1, *btv1, *Wv2, *bv2;
  const int   *ei;
};
struct NodeParams {
  const float *x;
  const float *Wh1, *bh1, *gh1, *bth1, *Wh2, *bh2;
  float       *out;
};

// ------------------------------- helpers -----------------------------------
__device__ __forceinline__ uint32_t smem_u32(const void* p) {
  uint32_t a;
  asm("{ .reg .u64 t; cvta.to.shared.u64 t, %1; cvt.u32.u64 %0, t; }"
      : "=r"(a) : "l"(p));
  return a;
}
__device__ __forceinline__ void ldsm4(uint32_t& a0, uint32_t& a1, uint32_t& a2,
                                      uint32_t& a3, uint32_t addr) {
  asm volatile(
      "ldmatrix.sync.aligned.m8n8.x4.shared.b16 {%0,%1,%2,%3}, [%4];"
      : "=r"(a0), "=r"(a1), "=r"(a2), "=r"(a3) : "r"(addr));
}
__device__ __forceinline__ void ldsm4t(uint32_t& a0, uint32_t& a1, uint32_t& a2,
                                       uint32_t& a3, uint32_t addr) {
  asm volatile(
      "ldmatrix.sync.aligned.m8n8.x4.trans.shared.b16 {%0,%1,%2,%3}, [%4];"
      : "=r"(a0), "=r"(a1), "=r"(a2), "=r"(a3) : "r"(addr));
}
__device__ __forceinline__ void mma16816(float* c, uint32_t a0, uint32_t a1,
                                         uint32_t a2, uint32_t a3, uint32_t b0,
                                         uint32_t b1) {
  asm volatile(
      "mma.sync.aligned.m16n8k16.row.col.f32.f16.f16.f32 "
      "{%0,%1,%2,%3}, {%4,%5,%6,%7}, {%8,%9}, {%0,%1,%2,%3};"
      : "+f"(c[0]), "+f"(c[1]), "+f"(c[2]), "+f"(c[3])
      : "r"(a0), "r"(a1), "r"(a2), "r"(a3), "r"(b0), "r"(b1));
}
__device__ __forceinline__ void red4(float* p, float a, float b, float c,
                                     float d) {
  asm volatile("red.global.add.v4.f32 [%0], {%1,%2,%3,%4};"
               :: "l"(p), "f"(a), "f"(b), "f"(c), "f"(d) : "memory");
}
__device__ __forceinline__ void red2(float* p, float a, float b) {
  asm volatile("red.global.add.v2.f32 [%0], {%1,%2};"
               :: "l"(p), "f"(a), "f"(b) : "memory");
}
// byte offset in an N-row x 128-col fp16 tile: 256B rows, 16B-chunk xor swizzle
__device__ __forceinline__ uint32_t swb(int row, int col) {
  return (uint32_t)row * 256u + (uint32_t)((((col >> 3) ^ (row & 7)) & 15) << 4) +
         (uint32_t)((col & 7) << 1);
}
__device__ __forceinline__ uint32_t h2pack(float a, float b) {
  __half2 h = __floats2half2_rn(a, b);
  return (uint32_t)__half_as_ushort(__low2half(h)) |
         ((uint32_t)__half_as_ushort(__high2half(h)) << 16);
}
__device__ __forceinline__ float softplus_f(float v) {
  return fmaxf(v, 0.f) + __logf(1.f + __expf(-fabsf(v)));
}

// acc[16][4] = rows [m0..m0+15] of (Atile @ Wtile); K=128, optional K-ext.
template <bool EXT>
__device__ __forceinline__ void warp_gemm(uint32_t smA, uint32_t smW,
                                          uint32_t smAx, uint32_t smWx,
                                          int m0, int lane, float acc[16][4]) {
#pragma unroll
  for (int f = 0; f < 16; ++f)
#pragma unroll
    for (int e = 0; e < 4; ++e) acc[f][e] = 0.f;

  const int mid = lane >> 3;
  const int wi  = lane & 7;
  const int arow = m0 + wi + (mid & 1) * 8;
  const uint32_t arow_base = smA + (uint32_t)arow * 256u;
  const int ar7 = arow & 7;

#pragma unroll
  for (int k = 0; k < 8; ++k) {
    const int k0 = k * 16;
    int cha = (k0 >> 3) + (mid >> 1);
    uint32_t a0, a1, a2, a3;
    ldsm4(a0, a1, a2, a3, arow_base + (uint32_t)(((cha ^ ar7) & 15) << 4));
    const int krow = k0 + wi + (mid & 1) * 8;
    const uint32_t brow_base = smW + (uint32_t)krow * 256u;
    const int kr7 = krow & 7;
#pragma unroll
    for (int nf2 = 0; nf2 < 8; ++nf2) {
      int chb = (nf2 << 1) + (mid >> 1);
      uint32_t b0, b1, b2, b3;
      ldsm4t(b0, b1, b2, b3, brow_base + (uint32_t)(((chb ^ kr7) & 15) << 4));
      mma16816(acc[2 * nf2],     a0, a1, a2, a3, b0, b1);
      mma16816(acc[2 * nf2 + 1], a0, a1, a2, a3, b2, b3);
    }
  }
  if (EXT) {
    uint32_t a0, a1, a2, a3;
    ldsm4(a0, a1, a2, a3,
          smAx + (uint32_t)arow * 48u + (uint32_t)((mid >> 1) << 4));
    const int krowe = wi + (mid & 1) * 8;
    const uint32_t brow_base = smWx + (uint32_t)krowe * 256u;
    const int kr7e = krowe & 7;
#pragma unroll
    for (int nf2 = 0; nf2 < 8; ++nf2) {
      int chb = (nf2 << 1) + (mid >> 1);
      uint32_t b0, b1, b2, b3;
      ldsm4t(b0, b1, b2, b3, brow_base + (uint32_t)(((chb ^ kr7e) & 15) << 4));
      mma16816(acc[2 * nf2],     a0, a1, a2, a3, b0, b1);
      mma16816(acc[2 * nf2 + 1], a0, a1, a2, a3, b2, b3);
    }
  }
}

__global__ void zero_kernel() {
  int i = blockIdx.x * 256 + threadIdx.x;
  if (i < NNODES * H) g_mh[i] = 0.f;
  if (i < NNODES * 2) g_mv[i] = 0.f;
  if (i < NNODES)     g_cnt[i] = 0.f;
}

// ------------------------------ edge kernel --------------------------------
__global__ void __launch_bounds__(512, 1) edge_kernel(EdgeParams p) {
  extern __shared__ __align__(1024) char sm[];
  const int tid  = threadIdx.x;
  const int wid  = tid >> 5;
  const int lane = tid & 31;

  // ---------------- prologue: weights / params into smem -----------------
  {
    const float* Wm[4] = {p.We1, p.Wv1, p.We2, p.We3};
#pragma unroll 1
    for (int m = 0; m < 4; ++m) {
      const float* W = Wm[m];
      char* base = sm + m * 32768;
      for (int i = tid; i < 4096; i += 512) {
        int k  = i >> 5;
        int c4 = (i & 31) << 2;
        float4 w = *(const float4*)(W + k * 128 + c4);
        uint2 pk;
        pk.x = h2pack(w.x, w.y);
        pk.y = h2pack(w.z, w.w);
        *(uint2*)(base + swb(k, c4)) = pk;
      }
    }
    const float* Wx[2] = {p.We1, p.Wv1};
    const int    Ox[2] = {OWX_E1, OWX_V1};
#pragma unroll 1
    for (int m = 0; m < 2; ++m) {
      const float* W = Wx[m];
      char* base = sm + Ox[m];
      for (int i = tid; i < 512; i += 512) {
        int row = i >> 5;
        int c4  = (i & 31) << 2;
        float sc = (row == 4) ? 4.f : 1.f;
        float w0 = 0.f, w1 = 0.f, w2 = 0.f, w3 = 0.f;
        if (row < 5) {
          const float* wr = W + (128 + row) * 128 + c4;
          w0 = wr[0] * sc; w1 = wr[1] * sc; w2 = wr[2] * sc; w3 = wr[3] * sc;
        }
        uint2 pk;
        pk.x = h2pack(w0, w1);
        pk.y = h2pack(w2, w3);
        *(uint2*)(base + swb(row, c4)) = pk;
      }
    }
    if (tid < 128) {
      ((float*)(sm + O_BE1))[tid]  = p.be1[tid];
      ((float*)(sm + O_GE1))[tid]  = p.ge1[tid];
      ((float*)(sm + O_BTE1))[tid] = p.bte1[tid];
      ((float*)(sm + O_BV1))[tid]  = p.bv1[tid];
      ((float*)(sm + O_GV1))[tid]  = p.gv1[tid];
      ((float*)(sm + O_BTV1))[tid] = p.btv1[tid];
      ((float*)(sm + O_WV2))[tid]  = p.Wv2[tid];
      ((float*)(sm + O_BE2))[tid]  = p.be2[tid];
      ((float*)(sm + O_BE3))[tid]  = p.be3[tid];
    }
    if (tid == 0) ((float*)(sm + O_BV2))[0] = p.bv2[0];
  }
  __syncthreads();

  const uint32_t smb  = smem_u32(sm);
  const uint32_t bufA = smb + OACTA;
  const uint32_t bufAx= smb + OACTX;
  const uint32_t wE1  = smb + OW_E1;
  const uint32_t wV1  = smb + OW_V1;
  const uint32_t wE2  = smb + OW_E2;
  const uint32_t wE3  = smb + OW_E3;
  const uint32_t wxE1 = smb + OWX_E1;
  const uint32_t wxV1 = smb + OWX_V1;

  int*   sDst = (int*)(sm + O_DST);
  float* sRel = (float*)(sm + O_REL);
  const float* cBE1 = (const float*)(sm + O_BE1);
  const float* cGE1 = (const float*)(sm + O_GE1);
  const float* cBT1 = (const float*)(sm + O_BTE1);
  const float* cBV1 = (const float*)(sm + O_BV1);
  const float* cGV1 = (const float*)(sm + O_GV1);
  const float* cBTV = (const float*)(sm + O_BTV1);
  const float* cWV2 = (const float*)(sm + O_WV2);
  const float* cBE2 = (const float*)(sm + O_BE2);
  const float* cBE3 = (const float*)(sm + O_BE3);

  const int g  = lane >> 2;
  const int q  = lane & 3;
  const int m0 = wid * 16;
  const int rA = m0 + g;
  const int rB = rA + 8;

  float acc[16][4];

#pragma unroll 1
  for (int tile = blockIdx.x; tile < NTILES; tile += gridDim.x) {
    __syncthreads();  // bufA/bufAx/sDst free (all warps past E3 reads)
    const int e0 = tile * ETILE;

    // ------------- geometry (threads 0..255), in parallel with gather ------
    if (tid < ETILE) {
      int e = e0 + tid;
      int s = p.ei[e], d = p.ei[NEDGES + e];
      sDst[tid] = d;
      float2 ps = ((const float2*)p.pos)[s], pd = ((const float2*)p.pos)[d];
      float2 vs = ((const float2*)p.vel)[s], vd = ((const float2*)p.vel)[d];
      float rpx = ps.x - pd.x, rpy = ps.y - pd.y;
      float rvx = vs.x - vd.x, rvy = vs.y - vd.y;
      float dist = rpx * rpx + rpy * rpy;
      float dvr  = rvx * rpx + rvy * rpy;
      float r2   = fminf(1.f / (dist + 0.05f), 20.f);
      float r6   = fminf(r2 * r2 * r2, 400.f);
      float r12  = fminf(r6 * r6, 160000.f);
      uint4 lo;
      lo.x = h2pack(dist, dvr);
      lo.y = h2pack(r2, r6);
      lo.z = h2pack(r12 * 0.25f, 0.f);
      lo.w = 0u;
      *(uint4*)(sm + OACTX + tid * 48)      = lo;
      *(uint4*)(sm + OACTX + tid * 48 + 16) = make_uint4(0u, 0u, 0u, 0u);
      sRel[2 * tid]     = rpx;
      sRel[2 * tid + 1] = rpy;
    }

    // ------------- gather (all 512 threads; indices direct from ei) --------
#pragma unroll 1
    for (int b = 0; b < 2; ++b) {
      float4 vreg[8];
      int    eidx[8], col4[8];
#pragma unroll
      for (int u = 0; u < 8; ++u) {
        int i = tid + (b * 8 + u) * 512;
        int e = i >> 5, qq = i & 31;
        int half = qq >> 4, c4 = qq & 15;
        int node = p.ei[(half ? 0 : NEDGES) + e0 + e];
        eidx[u] = e;
        col4[u] = half * 64 + c4 * 4;
        vreg[u] = ((const float4*)p.x)[node * 16 + c4];
      }
#pragma unroll
      for (int u = 0; u < 8; ++u) {
        uint2 pk;
        pk.x = h2pack(vreg[u].x, vreg[u].y);
        pk.y = h2pack(vreg[u].z, vreg[u].w);
        *(uint2*)(sm + OACTA + swb(eidx[u], col4[u])) = pk;
      }
    }
    __syncthreads();

    // ================= stage 1: V = [A|feat] @ Wv1 (K=144) =================
    warp_gemm<true>(bufA, wV1, bufAx, wxV1, m0, lane, acc);
    {
      float sa = 0.f, s2a = 0.f, sb = 0.f, s2b = 0.f;
#pragma unroll
      for (int f = 0; f < 16; ++f) {
#pragma unroll
        for (int t = 0; t < 2; ++t) {
          int c = 8 * f + 2 * q + t;
          float bb = cBV1[c];
          float za = acc[f][t] + bb;
          float zb = acc[f][2 + t] + bb;
          acc[f][t] = za;
          acc[f][2 + t] = zb;
          sa += za; s2a = fmaf(za, za, s2a);
          sb += zb; s2b = fmaf(zb, zb, s2b);
        }
      }
#pragma unroll
      for (int m = 1; m < 4; m <<= 1) {
        sa  += __shfl_xor_sync(0xffffffffu, sa, m);
        s2a += __shfl_xor_sync(0xffffffffu, s2a, m);
        sb  += __shfl_xor_sync(0xffffffffu, sb, m);
        s2b += __shfl_xor_sync(0xffffffffu, s2b, m);
      }
      float mua = sa * (1.f / 128.f);
      float ria = rsqrtf(s2a * (1.f / 128.f) - mua * mua + 1e-5f);
      float mub = sb * (1.f / 128.f);
      float rib = rsqrtf(s2b * (1.f / 128.f) - mub * mub + 1e-5f);
      float va = 0.f, vb = 0.f;
#pragma unroll
      for (int f = 0; f < 16; ++f) {
#pragma unroll
        for (int t = 0; t < 2; ++t) {
          int c = 8 * f + 2 * q + t;
          float gv = cGV1[c], bt = cBTV[c], wv = cWV2[c];
          va += softplus_f((acc[f][t] - mua) * ria * gv + bt) * wv;
          vb += softplus_f((acc[f][2 + t] - mub) * rib * gv + bt) * wv;
        }
      }
#pragma unroll
      for (int m = 1; m < 4; m <<= 1) {
        va += __shfl_xor_sync(0xffffffffu, va, m);
        vb += __shfl_xor_sync(0xffffffffu, vb, m);
      }
      if (q == 0) {
        float bv2v = ((const float*)(sm + O_BV2))[0];
        int dA = sDst[rA];
        float vwa = va + bv2v;
        red2(&g_mv[2 * dA], vwa * sRel[2 * rA], vwa * sRel[2 * rA + 1]);
        atomicAdd(&g_cnt[dA], 1.f);
        int dB = sDst[rB];
        float vwb = vb + bv2v;
        red2(&g_mv[2 * dB], vwb * sRel[2 * rB], vwb * sRel[2 * rB + 1]);
        atomicAdd(&g_cnt[dB], 1.f);
      }
    }

    // ================= stage 2: E1 = [A|feat] @ We1 -> H1 in place =========
    warp_gemm<true>(bufA, wE1, bufAx, wxE1, m0, lane, acc);
    {
      float sa = 0.f, s2a = 0.f, sb = 0.f, s2b = 0.f;
#pragma unroll
      for (int f = 0; f < 16; ++f) {
#pragma unroll
        for (int t = 0; t < 2; ++t) {
          int c = 8 * f + 2 * q + t;
          float bb = cBE1[c];
          float za = acc[f][t] + bb;
          float zb = acc[f][2 + t] + bb;
          acc[f][t] = za;
          acc[f][2 + t] = zb;
          sa += za; s2a = fmaf(za, za, s2a);
          sb += zb; s2b = fmaf(zb, zb, s2b);
        }
      }
#pragma unroll
      for (int m = 1; m < 4; m <<= 1) {
        sa  += __shfl_xor_sync(0xffffffffu, sa, m);
        s2a += __shfl_xor_sync(0xffffffffu, s2a, m);
        sb  += __shfl_xor_sync(0xffffffffu, sb, m);
        s2b += __shfl_xor_sync(0xffffffffu, s2b, m);
      }
      float mua = sa * (1.f / 128.f);
      float ria = rsqrtf(s2a * (1.f / 128.f) - mua * mua + 1e-5f);
      float mub = sb * (1.f / 128.f);
      float rib = rsqrtf(s2b * (1.f / 128.f) - mub * mub + 1e-5f);
#pragma unroll
      for (int f = 0; f < 16; ++f) {
        int c0 = 8 * f + 2 * q;
        float ha0 = softplus_f((acc[f][0] - mua) * ria * cGE1[c0] + cBT1[c0]);
        float ha1 = softplus_f((acc[f][1] - mua) * ria * cGE1[c0 + 1] + cBT1[c0 + 1]);
        float hb0 = softplus_f((acc[f][2] - mub) * rib * cGE1[c0] + cBT1[c0]);
        float hb1 = softplus_f((acc[f][3] - mub) * rib * cGE1[c0 + 1] + cBT1[c0 + 1]);
        *(uint32_t*)(sm + OACTA + swb(rA, c0)) = h2pack(ha0, ha1);
        *(uint32_t*)(sm + OACTA + swb(rB, c0)) = h2pack(hb0, hb1);
      }
    }

    // ================= stage 3: E2 = H1 @ We2 -> H2 in place ===============
    __syncwarp();
    warp_gemm<false>(bufA, wE2, 0, 0, m0, lane, acc);
    {
#pragma unroll
      for (int f = 0; f < 16; ++f) {
        int c0 = 8 * f + 2 * q;
        float b0 = cBE2[c0], b1 = cBE2[c0 + 1];
        float ha0 = softplus_f(acc[f][0] + b0);
        float ha1 = softplus_f(acc[f][1] + b1);
        float hb0 = softplus_f(acc[f][2] + b0);
        float hb1 = softplus_f(acc[f][3] + b1);
        *(uint32_t*)(sm + OACTA + swb(rA, c0)) = h2pack(ha0, ha1);
        *(uint32_t*)(sm + OACTA + swb(rB, c0)) = h2pack(hb0, hb1);
      }
    }

    // ================= stage 4: E3 = H2 @ We3 -> vectorized scatter ========
    __syncwarp();
    warp_gemm<false>(bufA, wE3, 0, 0, m0, lane, acc);
    {
      int dA = sDst[rA], dB = sDst[rB];
      float* gpa = g_mh + dA * H;
      float* gpb = g_mh + dB * H;
      const bool odd = (q & 1);
#pragma unroll
      for (int f = 0; f < 16; ++f) {
        int c0 = 8 * f + 2 * q;
        float b0 = cBE3[c0], b1 = cBE3[c0 + 1];
        float a0 = acc[f][0] + b0;
        float a1 = acc[f][1] + b1;
        float a2 = acc[f][2] + b0;
        float a3 = acc[f][3] + b1;
        float u0 = __shfl_xor_sync(0xffffffffu, odd ? a0 : a2, 1);
        float u1 = __shfl_xor_sync(0xffffffffu, odd ? a1 : a3, 1);
        float* ptr = odd ? (gpb + c0 - 2) : (gpa + c0);
        float v0 = odd ? u0 : a0;
        float v1 = odd ? u1 : a1;
        float v2 = odd ? a2 : u0;
        float v3 = odd ? a3 : u1;
        red4(ptr, v0, v1, v2, v3);
      }
    }
  }
}

// ------------------------------ node kernel --------------------------------
template <int STRIDE, int KACT, int NCHUNK>
__device__ __forceinline__ void gemm_tile(const float* __restrict__ W,
                                          const float* sA_, float* sB_,
                                          float acc[8][8], int tx, int ty,
                                          int tid) {
  int wrow = tid >> 5, wc4 = tid & 31;
  float4 v;
  {
    int k = wrow;
    v = (k < KACT) ? reinterpret_cast<const float4*>(W)[k * 32 + wc4]
                   : make_float4(0.f, 0.f, 0.f, 0.f);
  }
#pragma unroll 1
  for (int ch = 0; ch < NCHUNK; ++ch) {
    reinterpret_cast<float4*>(sB_)[tid] = v;
    __syncthreads();
    if (ch + 1 < NCHUNK) {
      int k = (ch + 1) * 8 + wrow;
      v = (k < KACT) ? reinterpret_cast<const float4*>(W)[k * 32 + wc4]
                     : make_float4(0.f, 0.f, 0.f, 0.f);
    }
    int k0 = ch * 8;
#pragma unroll
    for (int kk = 0; kk < 8; ++kk) {
      float a[8];
#pragma unroll
      for (int r = 0; r < 8; ++r) a[r] = sA_[(ty * 8 + r) * STRIDE + k0 + kk];
      const float4* bp = reinterpret_cast<const float4*>(sB_ + kk * 128 + tx * 8);
      float4 b0 = bp[0], b1 = bp[1];
      float b[8] = {b0.x, b0.y, b0.z, b0.w, b1.x, b1.y, b1.z, b1.w};
#pragma unroll
      for (int r = 0; r < 8; ++r)
#pragma unroll
        for (int c = 0; c < 8; ++c) acc[r][c] = fmaf(a[r], b[c], acc[r][c]);
    }
    __syncthreads();
  }
}

__global__ void __launch_bounds__(256, 1) node_kernel(NodeParams p) {
  extern __shared__ float smem_dyn[];
  float* sA   = smem_dyn;
  float* sH   = sA + 128 * KHP;
  float* sB   = sH + 128 * H;
  float* sDen = sB + 8 * H;

  int tid = threadIdx.x;
  int tx = tid & 15, ty = tid >> 4;
  int n0 = blockIdx.x * 128;

  for (int i = tid; i < 128 * KHP; i += 256) sA[i] = 0.f;
  __syncthreads();
  if (tid < 128) {
    int n = n0 + tid;
    float den = 1.f, nrm = 0.f;
    if (n < NNODES) {
      den = fmaxf(g_cnt[n], 1.f);
      float mvx = g_mv[2 * n] / den + 1e-8f;
      float mvy = g_mv[2 * n + 1] / den + 1e-8f;
      nrm = sqrtf(mvx * mvx + mvy * mvy);
    }
    sDen[tid] = den;
    sA[tid * KHP + 192] = nrm;
  }
  __syncthreads();
  for (int i = tid; i < 128 * 64; i += 256) {
    int r = i >> 6, c = i & 63;
    int n = n0 + r;
    if (n < NNODES) sA[r * KHP + c] = p.x[n * 64 + c];
  }
  for (int i = tid; i < 128 * H; i += 256) {
    int r = i >> 7, c = i & 127;
    int n = n0 + r;
    if (n < NNODES) sA[r * KHP + 64 + c] = g_mh[n * 128 + c] / sDen[r];
  }
  __syncthreads();

  float acc[8][8];
#pragma unroll
  for (int r = 0; r < 8; ++r)
#pragma unroll
    for (int c = 0; c < 8; ++c) acc[r][c] = 0.f;
  gemm_tile<KHP, KH, 25>(p.Wh1, sA, sB, acc, tx, ty, tid);
  {
    float bias[8], g[8], bt[8];
#pragma unroll
    for (int c = 0; c < 8; ++c) {
      int col = tx * 8 + c;
      bias[c] = p.bh1[col]; g[c] = p.gh1[col]; bt[c] = p.bth1[col];
    }
#pragma unroll
    for (int r = 0; r < 8; ++r) {
      float z[8], s = 0.f, s2 = 0.f;
#pragma unroll
      for (int c = 0; c < 8; ++c) {
        z[c] = acc[r][c] + bias[c];
        s += z[c]; s2 += z[c] * z[c];
      }
#pragma unroll
      for (int m = 1; m < 16; m <<= 1) {
        s  += __shfl_xor_sync(0xffffffffu, s, m);
        s2 += __shfl_xor_sync(0xffffffffu, s2, m);
      }
      float mu = s * (1.f / 128.f);
      float var = s2 * (1.f / 128.f) - mu * mu;
      float rinv = rsqrtf(var + 1e-5f);
      int row = ty * 8 + r;
#pragma unroll
      for (int c = 0; c < 8; ++c)
        sH[row * H + tx * 8 + c] =
            softplus_f((z[c] - mu) * rinv * g[c] + bt[c]);
    }
  }
  __syncthreads();

  float acc2[8][4];
#pragma unroll
  for (int r = 0; r < 8; ++r)
#pragma unroll
    for (int c = 0; c < 4; ++c) acc2[r][c] = 0.f;
#pragma unroll 1
  for (int ch = 0; ch < 16; ++ch) {
    int k0 = ch * 8;
    if (tid < 128) {
      reinterpret_cast<float4*>(sB)[tid] =
          reinterpret_cast<const float4*>(p.Wh2)[(k0 + (tid >> 4)) * 16 +
                                                 (tid & 15)];
    }
    __syncthreads();
#pragma unroll
    for (int kk = 0; kk < 8; ++kk) {
      float a[8];
#pragma unroll
      for (int r = 0; r < 8; ++r) a[r] = sH[(ty * 8 + r) * H + k0 + kk];
      float4 b4 = reinterpret_cast<const float4*>(sB + kk * 64 + tx * 4)[0];
      float b[4] = {b4.x, b4.y, b4.z, b4.w};
#pragma unroll
      for (int r = 0; r < 8; ++r)
#pragma unroll
        for (int c = 0; c < 4; ++c) acc2[r][c] = fmaf(a[r], b[c], acc2[r][c]);
    }
    __syncthreads();
  }
  float bias2[4];
#pragma unroll
  for (int c = 0; c < 4; ++c) bias2[c] = p.bh2[tx * 4 + c];
#pragma unroll
  for (int r = 0; r < 8; ++r) {
    int n = n0 + ty * 8 + r;
    if (n < NNODES) {
#pragma unroll
      for (int c = 0; c < 4; ++c) {
        int col = tx * 4 + c;
        p.out[n * 64 + col] = p.x[n * 64 + col] + acc2[r][c] + bias2[c];
      }
    }
  }
}

// ------------------------------ launch -------------------------------------
extern "C" void kernel_launch(void* const* d_in, const int* in_sizes, int n_in,
                              void* d_out, int out_size) {
  EdgeParams ep;
  ep.x    = (const float*)d_in[0];
  ep.pos  = (const float*)d_in[1];
  ep.vel  = (const float*)d_in[2];
  ep.We1  = (const float*)d_in[3];
  ep.be1  = (const float*)d_in[4];
  ep.ge1  = (const float*)d_in[5];
  ep.bte1 = (const float*)d_in[6];
  ep.We2  = (const float*)d_in[7];
  ep.be2  = (const float*)d_in[8];
  ep.We3  = (const float*)d_in[9];
  ep.be3  = (const float*)d_in[10];
  ep.Wv1  = (const float*)d_in[11];
  ep.bv1  = (const float*)d_in[12];
  ep.gv1  = (const float*)d_in[13];
  ep.btv1 = (const float*)d_in[14];
  ep.Wv2  = (const float*)d_in[15];
  ep.bv2  = (const float*)d_in[16];
  ep.ei   = (const int*)d_in[23];

  NodeParams np;
  np.x    = ep.x;
  np.Wh1  = (const float*)d_in[17];
  np.bh1  = (const float*)d_in[18];
  np.gh1  = (const float*)d_in[19];
  np.bth1 = (const float*)d_in[20];
  np.Wh2  = (const float*)d_in[21];
  np.bh2  = (const float*)d_in[22];
  np.out  = (float*)d_out;

  int node_smem = (128 * KHP + 128 * H + 8 * H + 128) * (int)sizeof(float);
  cudaFuncSetAttribute(edge_kernel, cudaFuncAttributeMaxDynamicSharedMemorySize,
                       EDGE_SMEM);
  cudaFuncSetAttribute(node_kernel, cudaFuncAttributeMaxDynamicSharedMemorySize,
                       node_smem);

  zero_kernel<<<(NNODES * H + 255) / 256, 256>>>();
  edge_kernel<<<148, 512, EDGE_SMEM>>>(ep);
  node_kernel<<<(NNODES + 127) / 128, 256, node_smem>>>(np);
}

// round 10
// speedup vs baseline: 6.8849x; 1.1411x over previous
#include <cuda_runtime.h>
#include <cuda_fp16.h>
#include <cstdint>

// ---------------------------------------------------------------------------
// R8: R7 + cross-tile gather prefetch in edge kernel + HMMA node kernel.
//   Edge: prefetch next tile's geometry, batch-0 x rows and batch-1 node
//         indices before the loop-top barrier (hides LDG latency).
//   Node: phi_h on mma.sync: K=193 split into two 128-col A tiles
//         ([x|mh0:63], [mh64:127|nrm|0]) + reordered Wh1 tiles, LN+softplus
//         in place, Wh2 N=64 GEMM + residual. 79 CTAs x 256 rows.
// ---------------------------------------------------------------------------

namespace {
constexpr int NNODES = 20000;
constexpr int NEDGES = 640000;
constexpr int H      = 128;
constexpr int ETILE  = 256;
constexpr int NTILES = NEDGES / ETILE;   // 2500

// ---- edge smem layout ----
constexpr int OW_E1  = 0;
constexpr int OW_V1  = 32768;
constexpr int OW_E2  = 65536;
constexpr int OW_E3  = 98304;
constexpr int OWX_E1 = 131072;
constexpr int OWX_V1 = 135168;
constexpr int OACTA  = 139264;   // 256 rows x 256 B
constexpr int OACTX  = 204800;   // 256 rows x 48 B
constexpr int O_BE1  = 217088;
constexpr int O_GE1  = 217600;
constexpr int O_BTE1 = 218112;
constexpr int O_BV1  = 218624;
constexpr int O_GV1  = 219136;
constexpr int O_BTV1 = 219648;
constexpr int O_WV2  = 220160;
constexpr int O_BE2  = 220672;
constexpr int O_BE3  = 221184;
constexpr int O_REL  = 221696;
constexpr int O_DST  = 223744;
constexpr int O_BV2  = 224768;
constexpr int EDGE_SMEM = 224896;

// ---- node smem layout ----
constexpr int ON_A1   = 0;        // 256 x 256B = 64 KB  (x | mh0:63) -> H
constexpr int ON_A2   = 65536;    // 64 KB (mh64:127 | nrm | 0)
constexpr int ON_W1a  = 131072;   // 32 KB  Wh1 rows 0..127
constexpr int ON_W1b  = 163840;   // 32 KB  Wh1 rows 128..192 + zeros
constexpr int ON_W2   = 196608;   // 32 KB  Wh2 (cols 64..127 zero)
constexpr int ON_BH1  = 229376;
constexpr int ON_GH1  = 229888;
constexpr int ON_BTH1 = 230400;
constexpr int ON_BH2  = 230912;   // 256 B
constexpr int ON_RDEN = 231168;   // 256 x 4 B
constexpr int NODE_SMEM = 232192;
constexpr int NODE_CTAS = (NNODES + 255) / 256;  // 79
}  // namespace

__device__ __align__(16) float g_mh[NNODES * H];
__device__ __align__(16) float g_mv[NNODES * 2];
__device__ float g_cnt[NNODES];

struct EdgeParams {
  const float *x, *pos, *vel;
  const float *We1, *be1, *ge1, *bte1, *We2, *be2, *We3, *be3;
  const float *Wv1, *bv1, *gv1, *btv1, *Wv2, *bv2;
  const int   *ei;
};
struct NodeParams {
  const float *x;
  const float *Wh1, *bh1, *gh1, *bth1, *Wh2, *bh2;
  float       *out;
};

// ------------------------------- helpers -----------------------------------
__device__ __forceinline__ uint32_t smem_u32(const void* p) {
  uint32_t a;
  asm("{ .reg .u64 t; cvta.to.shared.u64 t, %1; cvt.u32.u64 %0, t; }"
      : "=r"(a) : "l"(p));
  return a;
}
__device__ __forceinline__ void ldsm4(uint32_t& a0, uint32_t& a1, uint32_t& a2,
                                      uint32_t& a3, uint32_t addr) {
  asm volatile(
      "ldmatrix.sync.aligned.m8n8.x4.shared.b16 {%0,%1,%2,%3}, [%4];"
      : "=r"(a0), "=r"(a1), "=r"(a2), "=r"(a3) : "r"(addr));
}
__device__ __forceinline__ void ldsm4t(uint32_t& a0, uint32_t& a1, uint32_t& a2,
                                       uint32_t& a3, uint32_t addr) {
  asm volatile(
      "ldmatrix.sync.aligned.m8n8.x4.trans.shared.b16 {%0,%1,%2,%3}, [%4];"
      : "=r"(a0), "=r"(a1), "=r"(a2), "=r"(a3) : "r"(addr));
}
__device__ __forceinline__ void mma16816(float* c, uint32_t a0, uint32_t a1,
                                         uint32_t a2, uint32_t a3, uint32_t b0,
                                         uint32_t b1) {
  asm volatile(
      "mma.sync.aligned.m16n8k16.row.col.f32.f16.f16.f32 "
      "{%0,%1,%2,%3}, {%4,%5,%6,%7}, {%8,%9}, {%0,%1,%2,%3};"
      : "+f"(c[0]), "+f"(c[1]), "+f"(c[2]), "+f"(c[3])
      : "r"(a0), "r"(a1), "r"(a2), "r"(a3), "r"(b0), "r"(b1));
}
__device__ __forceinline__ void red4(float* p, float a, float b, float c,
                                     float d) {
  asm volatile("red.global.add.v4.f32 [%0], {%1,%2,%3,%4};"
               :: "l"(p), "f"(a), "f"(b), "f"(c), "f"(d) : "memory");
}
__device__ __forceinline__ void red2(float* p, float a, float b) {
  asm volatile("red.global.add.v2.f32 [%0], {%1,%2};"
               :: "l"(p), "f"(a), "f"(b) : "memory");
}
__device__ __forceinline__ uint32_t swb(int row, int col) {
  return (uint32_t)row * 256u + (uint32_t)((((col >> 3) ^ (row & 7)) & 15) << 4) +
         (uint32_t)((col & 7) << 1);
}
__device__ __forceinline__ uint32_t h2pack(float a, float b) {
  __half2 h = __floats2half2_rn(a, b);
  return (uint32_t)__half_as_ushort(__low2half(h)) |
         ((uint32_t)__half_as_ushort(__high2half(h)) << 16);
}
__device__ __forceinline__ float softplus_f(float v) {
  return fmaxf(v, 0.f) + __logf(1.f + __expf(-fabsf(v)));
}

// acc[16][4] (+)= rows [m0..m0+15] of (Atile @ Wtile); K=128, optional K-ext.
template <bool EXT, bool ZERO>
__device__ __forceinline__ void warp_gemm(uint32_t smA, uint32_t smW,
                                          uint32_t smAx, uint32_t smWx,
                                          int m0, int lane, float acc[16][4]) {
  if (ZERO) {
#pragma unroll
    for (int f = 0; f < 16; ++f)
#pragma unroll
      for (int e = 0; e < 4; ++e) acc[f][e] = 0.f;
  }
  const int mid = lane >> 3;
  const int wi  = lane & 7;
  const int arow = m0 + wi + (mid & 1) * 8;
  const uint32_t arow_base = smA + (uint32_t)arow * 256u;
  const int ar7 = arow & 7;

#pragma unroll
  for (int k = 0; k < 8; ++k) {
    const int k0 = k * 16;
    int cha = (k0 >> 3) + (mid >> 1);
    uint32_t a0, a1, a2, a3;
    ldsm4(a0, a1, a2, a3, arow_base + (uint32_t)(((cha ^ ar7) & 15) << 4));
    const int krow = k0 + wi + (mid & 1) * 8;
    const uint32_t brow_base = smW + (uint32_t)krow * 256u;
    const int kr7 = krow & 7;
#pragma unroll
    for (int nf2 = 0; nf2 < 8; ++nf2) {
      int chb = (nf2 << 1) + (mid >> 1);
      uint32_t b0, b1, b2, b3;
      ldsm4t(b0, b1, b2, b3, brow_base + (uint32_t)(((chb ^ kr7) & 15) << 4));
      mma16816(acc[2 * nf2],     a0, a1, a2, a3, b0, b1);
      mma16816(acc[2 * nf2 + 1], a0, a1, a2, a3, b2, b3);
    }
  }
  if (EXT) {
    uint32_t a0, a1, a2, a3;
    ldsm4(a0, a1, a2, a3,
          smAx + (uint32_t)arow * 48u + (uint32_t)((mid >> 1) << 4));
    const int krowe = wi + (mid & 1) * 8;
    const uint32_t brow_base = smWx + (uint32_t)krowe * 256u;
    const int kr7e = krowe & 7;
#pragma unroll
    for (int nf2 = 0; nf2 < 8; ++nf2) {
      int chb = (nf2 << 1) + (mid >> 1);
      uint32_t b0, b1, b2, b3;
      ldsm4t(b0, b1, b2, b3, brow_base + (uint32_t)(((chb ^ kr7e) & 15) << 4));
      mma16816(acc[2 * nf2],     a0, a1, a2, a3, b0, b1);
      mma16816(acc[2 * nf2 + 1], a0, a1, a2, a3, b2, b3);
    }
  }
}

__global__ void zero_kernel() {
  int i = blockIdx.x * 256 + threadIdx.x;
  if (i < NNODES * H) g_mh[i] = 0.f;
  if (i < NNODES * 2) g_mv[i] = 0.f;
  if (i < NNODES)     g_cnt[i] = 0.f;
}

// ------------------------------ edge kernel --------------------------------
__global__ void __launch_bounds__(512, 1) edge_kernel(EdgeParams p) {
  extern __shared__ __align__(1024) char sm[];
  const int tid  = threadIdx.x;
  const int wid  = tid >> 5;
  const int lane = tid & 31;

  // ---------------- prologue ----------------
  {
    const float* Wm[4] = {p.We1, p.Wv1, p.We2, p.We3};
#pragma unroll 1
    for (int m = 0; m < 4; ++m) {
      const float* W = Wm[m];
      char* base = sm + m * 32768;
      for (int i = tid; i < 4096; i += 512) {
        int k  = i >> 5;
        int c4 = (i & 31) << 2;
        float4 w = *(const float4*)(W + k * 128 + c4);
        uint2 pk;
        pk.x = h2pack(w.x, w.y);
        pk.y = h2pack(w.z, w.w);
        *(uint2*)(base + swb(k, c4)) = pk;
      }
    }
    const float* Wx[2] = {p.We1, p.Wv1};
    const int    Ox[2] = {OWX_E1, OWX_V1};
#pragma unroll 1
    for (int m = 0; m < 2; ++m) {
      const float* W = Wx[m];
      char* base = sm + Ox[m];
      for (int i = tid; i < 512; i += 512) {
        int row = i >> 5;
        int c4  = (i & 31) << 2;
        float sc = (row == 4) ? 4.f : 1.f;
        float w0 = 0.f, w1 = 0.f, w2 = 0.f, w3 = 0.f;
        if (row < 5) {
          const float* wr = W + (128 + row) * 128 + c4;
          w0 = wr[0] * sc; w1 = wr[1] * sc; w2 = wr[2] * sc; w3 = wr[3] * sc;
        }
        uint2 pk;
        pk.x = h2pack(w0, w1);
        pk.y = h2pack(w2, w3);
        *(uint2*)(base + swb(row, c4)) = pk;
      }
    }
    if (tid < 128) {
      ((float*)(sm + O_BE1))[tid]  = p.be1[tid];
      ((float*)(sm + O_GE1))[tid]  = p.ge1[tid];
      ((float*)(sm + O_BTE1))[tid] = p.bte1[tid];
      ((float*)(sm + O_BV1))[tid]  = p.bv1[tid];
      ((float*)(sm + O_GV1))[tid]  = p.gv1[tid];
      ((float*)(sm + O_BTV1))[tid] = p.btv1[tid];
      ((float*)(sm + O_WV2))[tid]  = p.Wv2[tid];
      ((float*)(sm + O_BE2))[tid]  = p.be2[tid];
      ((float*)(sm + O_BE3))[tid]  = p.be3[tid];
    }
    if (tid == 0) ((float*)(sm + O_BV2))[0] = p.bv2[0];
  }

  const uint32_t smb  = smem_u32(sm);
  const uint32_t bufA = smb + OACTA;
  const uint32_t bufAx= smb + OACTX;
  const uint32_t wE1  = smb + OW_E1;
  const uint32_t wV1  = smb + OW_V1;
  const uint32_t wE2  = smb + OW_E2;
  const uint32_t wE3  = smb + OW_E3;
  const uint32_t wxE1 = smb + OWX_E1;
  const uint32_t wxV1 = smb + OWX_V1;

  int*   sDst = (int*)(sm + O_DST);
  float* sRel = (float*)(sm + O_REL);
  const float* cBE1 = (const float*)(sm + O_BE1);
  const float* cGE1 = (const float*)(sm + O_GE1);
  const float* cBT1 = (const float*)(sm + O_BTE1);
  const float* cBV1 = (const float*)(sm + O_BV1);
  const float* cGV1 = (const float*)(sm + O_GV1);
  const float* cBTV = (const float*)(sm + O_BTV1);
  const float* cWV2 = (const float*)(sm + O_WV2);
  const float* cBE2 = (const float*)(sm + O_BE2);
  const float* cBE3 = (const float*)(sm + O_BE3);

  const int g  = lane >> 2;
  const int q  = lane & 3;
  const int m0 = wid * 16;
  const int rA = m0 + g;
  const int rB = rA + 8;

  float acc[16][4];

  // prefetch registers (live across the loop-top barrier; acc is dead there)
  float4 vr0[8];
  int    nid1[8];
  int    pf_s = 0, pf_d = 0;
  float2 pf_ps, pf_pd, pf_vs, pf_vd;

  auto prefetch = [&](int t) {
    int e0p = t * ETILE;
    if (tid < ETILE) {
      pf_s  = p.ei[e0p + tid];
      pf_d  = p.ei[NEDGES + e0p + tid];
      pf_ps = ((const float2*)p.pos)[pf_s];
      pf_pd = ((const float2*)p.pos)[pf_d];
      pf_vs = ((const float2*)p.vel)[pf_s];
      pf_vd = ((const float2*)p.vel)[pf_d];
    }
#pragma unroll
    for (int u = 0; u < 8; ++u) {
      int i = tid + u * 512;
      int e = i >> 5, qq = i & 31;
      int half = qq >> 4, c4 = qq & 15;
      int node = p.ei[(half ? 0 : NEDGES) + e0p + e];
      vr0[u] = ((const float4*)p.x)[node * 16 + c4];
    }
#pragma unroll
    for (int u = 0; u < 8; ++u) {
      int i = tid + (8 + u) * 512;
      int e = i >> 5, qq = i & 31;
      int half = qq >> 4;
      nid1[u] = p.ei[(half ? 0 : NEDGES) + e0p + e];
    }
  };

  __syncthreads();  // prologue smem ready
  prefetch(blockIdx.x);

#pragma unroll 1
  for (int tile = blockIdx.x; tile < NTILES; tile += gridDim.x) {
    __syncthreads();  // bufA/bufAx/sDst free

    // ------------- store prefetched geometry -------------
    if (tid < ETILE) {
      sDst[tid] = pf_d;
      float rpx = pf_ps.x - pf_pd.x, rpy = pf_ps.y - pf_pd.y;
      float rvx = pf_vs.x - pf_vd.x, rvy = pf_vs.y - pf_vd.y;
      float dist = rpx * rpx + rpy * rpy;
      float dvr  = rvx * rpx + rvy * rpy;
      float r2   = fminf(1.f / (dist + 0.05f), 20.f);
      float r6   = fminf(r2 * r2 * r2, 400.f);
      float r12  = fminf(r6 * r6, 160000.f);
      uint4 lo;
      lo.x = h2pack(dist, dvr);
      lo.y = h2pack(r2, r6);
      lo.z = h2pack(r12 * 0.25f, 0.f);
      lo.w = 0u;
      *(uint4*)(sm + OACTX + tid * 48)      = lo;
      *(uint4*)(sm + OACTX + tid * 48 + 16) = make_uint4(0u, 0u, 0u, 0u);
      sRel[2 * tid]     = rpx;
      sRel[2 * tid + 1] = rpy;
    }
    // ------------- store batch0 (prefetched), load+store batch1 -------------
#pragma unroll
    for (int u = 0; u < 8; ++u) {
      int i = tid + u * 512;
      int e = i >> 5, qq = i & 31;
      int half = qq >> 4, c4 = qq & 15;
      uint2 pk;
      pk.x = h2pack(vr0[u].x, vr0[u].y);
      pk.y = h2pack(vr0[u].z, vr0[u].w);
      *(uint2*)(sm + OACTA + swb(e, half * 64 + c4 * 4)) = pk;
    }
    {
      float4 vr1[8];
#pragma unroll
      for (int u = 0; u < 8; ++u) {
        int i = tid + (8 + u) * 512;
        int c4 = i & 15;
        vr1[u] = ((const float4*)p.x)[nid1[u] * 16 + c4];
      }
#pragma unroll
      for (int u = 0; u < 8; ++u) {
        int i = tid + (8 + u) * 512;
        int e = i >> 5, qq = i & 31;
        int half = qq >> 4, c4 = qq & 15;
        uint2 pk;
        pk.x = h2pack(vr1[u].x, vr1[u].y);
        pk.y = h2pack(vr1[u].z, vr1[u].w);
        *(uint2*)(sm + OACTA + swb(e, half * 64 + c4 * 4)) = pk;
      }
    }
    __syncthreads();

    // ================= stage 1: V = [A|feat] @ Wv1 (K=144) =================
    warp_gemm<true, true>(bufA, wV1, bufAx, wxV1, m0, lane, acc);
    {
      float sa = 0.f, s2a = 0.f, sb = 0.f, s2b = 0.f;
#pragma unroll
      for (int f = 0; f < 16; ++f) {
#pragma unroll
        for (int t = 0; t < 2; ++t) {
          int c = 8 * f + 2 * q + t;
          float bb = cBV1[c];
          float za = acc[f][t] + bb;
          float zb = acc[f][2 + t] + bb;
          acc[f][t] = za;
          acc[f][2 + t] = zb;
          sa += za; s2a = fmaf(za, za, s2a);
          sb += zb; s2b = fmaf(zb, zb, s2b);
        }
      }
#pragma unroll
      for (int m = 1; m < 4; m <<= 1) {
        sa  += __shfl_xor_sync(0xffffffffu, sa, m);
        s2a += __shfl_xor_sync(0xffffffffu, s2a, m);
        sb  += __shfl_xor_sync(0xffffffffu, sb, m);
        s2b += __shfl_xor_sync(0xffffffffu, s2b, m);
      }
      float mua = sa * (1.f / 128.f);
      float ria = rsqrtf(s2a * (1.f / 128.f) - mua * mua + 1e-5f);
      float mub = sb * (1.f / 128.f);
      float rib = rsqrtf(s2b * (1.f / 128.f) - mub * mub + 1e-5f);
      float va = 0.f, vb = 0.f;
#pragma unroll
      for (int f = 0; f < 16; ++f) {
#pragma unroll
        for (int t = 0; t < 2; ++t) {
          int c = 8 * f + 2 * q + t;
          float gv = cGV1[c], bt = cBTV[c], wv = cWV2[c];
          va += softplus_f((acc[f][t] - mua) * ria * gv + bt) * wv;
          vb += softplus_f((acc[f][2 + t] - mub) * rib * gv + bt) * wv;
        }
      }
#pragma unroll
      for (int m = 1; m < 4; m <<= 1) {
        va += __shfl_xor_sync(0xffffffffu, va, m);
        vb += __shfl_xor_sync(0xffffffffu, vb, m);
      }
      if (q == 0) {
        float bv2v = ((const float*)(sm + O_BV2))[0];
        int dA = sDst[rA];
        float vwa = va + bv2v;
        red2(&g_mv[2 * dA], vwa * sRel[2 * rA], vwa * sRel[2 * rA + 1]);
        atomicAdd(&g_cnt[dA], 1.f);
        int dB = sDst[rB];
        float vwb = vb + bv2v;
        red2(&g_mv[2 * dB], vwb * sRel[2 * rB], vwb * sRel[2 * rB + 1]);
        atomicAdd(&g_cnt[dB], 1.f);
      }
    }

    // ================= stage 2: E1 -> H1 in place =================
    warp_gemm<true, true>(bufA, wE1, bufAx, wxE1, m0, lane, acc);
    {
      float sa = 0.f, s2a = 0.f, sb = 0.f, s2b = 0.f;
#pragma unroll
      for (int f = 0; f < 16; ++f) {
#pragma unroll
        for (int t = 0; t < 2; ++t) {
          int c = 8 * f + 2 * q + t;
          float bb = cBE1[c];
          float za = acc[f][t] + bb;
          float zb = acc[f][2 + t] + bb;
          acc[f][t] = za;
          acc[f][2 + t] = zb;
          sa += za; s2a = fmaf(za, za, s2a);
          sb += zb; s2b = fmaf(zb, zb, s2b);
        }
      }
#pragma unroll
      for (int m = 1; m < 4; m <<= 1) {
        sa  += __shfl_xor_sync(0xffffffffu, sa, m);
        s2a += __shfl_xor_sync(0xffffffffu, s2a, m);
        sb  += __shfl_xor_sync(0xffffffffu, sb, m);
        s2b += __shfl_xor_sync(0xffffffffu, s2b, m);
      }
      float mua = sa * (1.f / 128.f);
      float ria = rsqrtf(s2a * (1.f / 128.f) - mua * mua + 1e-5f);
      float mub = sb * (1.f / 128.f);
      float rib = rsqrtf(s2b * (1.f / 128.f) - mub * mub + 1e-5f);
#pragma unroll
      for (int f = 0; f < 16; ++f) {
        int c0 = 8 * f + 2 * q;
        float ha0 = softplus_f((acc[f][0] - mua) * ria * cGE1[c0] + cBT1[c0]);
        float ha1 = softplus_f((acc[f][1] - mua) * ria * cGE1[c0 + 1] + cBT1[c0 + 1]);
        float hb0 = softplus_f((acc[f][2] - mub) * rib * cGE1[c0] + cBT1[c0]);
        float hb1 = softplus_f((acc[f][3] - mub) * rib * cGE1[c0 + 1] + cBT1[c0 + 1]);
        *(uint32_t*)(sm + OACTA + swb(rA, c0)) = h2pack(ha0, ha1);
        *(uint32_t*)(sm + OACTA + swb(rB, c0)) = h2pack(hb0, hb1);
      }
    }

    // ================= stage 3: E2 -> H2 in place =================
    __syncwarp();
    warp_gemm<false, true>(bufA, wE2, 0, 0, m0, lane, acc);
    {
#pragma unroll
      for (int f = 0; f < 16; ++f) {
        int c0 = 8 * f + 2 * q;
        float b0 = cBE2[c0], b1 = cBE2[c0 + 1];
        float ha0 = softplus_f(acc[f][0] + b0);
        float ha1 = softplus_f(acc[f][1] + b1);
        float hb0 = softplus_f(acc[f][2] + b0);
        float hb1 = softplus_f(acc[f][3] + b1);
        *(uint32_t*)(sm + OACTA + swb(rA, c0)) = h2pack(ha0, ha1);
        *(uint32_t*)(sm + OACTA + swb(rB, c0)) = h2pack(hb0, hb1);
      }
    }

    // ================= stage 4: E3 -> scatter =================
    __syncwarp();
    warp_gemm<false, true>(bufA, wE3, 0, 0, m0, lane, acc);
    {
      int dA = sDst[rA], dB = sDst[rB];
      float* gpa = g_mh + dA * H;
      float* gpb = g_mh + dB * H;
      const bool odd = (q & 1);
#pragma unroll
      for (int f = 0; f < 16; ++f) {
        int c0 = 8 * f + 2 * q;
        float b0 = cBE3[c0], b1 = cBE3[c0 + 1];
        float a0 = acc[f][0] + b0;
        float a1 = acc[f][1] + b1;
        float a2 = acc[f][2] + b0;
        float a3 = acc[f][3] + b1;
        float u0 = __shfl_xor_sync(0xffffffffu, odd ? a0 : a2, 1);
        float u1 = __shfl_xor_sync(0xffffffffu, odd ? a1 : a3, 1);
        float* ptr = odd ? (gpb + c0 - 2) : (gpa + c0);
        float v0 = odd ? u0 : a0;
        float v1 = odd ? u1 : a1;
        float v2 = odd ? a2 : u0;
        float v3 = odd ? a3 : u1;
        red4(ptr, v0, v1, v2, v3);
      }
    }

    // ------------- prefetch next tile (hides LDG latency behind barrier) ---
    int nt = tile + gridDim.x;
    if (nt < NTILES) prefetch(nt);
  }
}

// ------------------------------ node kernel (HMMA) --------------------------
__global__ void __launch_bounds__(512, 1) node_kernel(NodeParams p) {
  extern __shared__ __align__(1024) char sm[];
  const int tid  = threadIdx.x;
  const int wid  = tid >> 5;
  const int lane = tid & 31;
  const int n0   = blockIdx.x * 256;

  // ---------------- prologue: weights ----------------
  {
    // W1a: Wh1 rows 0..127
    for (int i = tid; i < 4096; i += 512) {
      int k  = i >> 5;
      int c4 = (i & 31) << 2;
      float4 w = *(const float4*)(p.Wh1 + k * 128 + c4);
      uint2 pk;
      pk.x = h2pack(w.x, w.y);
      pk.y = h2pack(w.z, w.w);
      *(uint2*)(sm + ON_W1a + swb(k, c4)) = pk;
    }
    // W1b: rows 0..64 = Wh1 rows 128..192; rows 65..127 = 0
    for (int i = tid; i < 4096; i += 512) {
      int k  = i >> 5;
      int c4 = (i & 31) << 2;
      float4 w = make_float4(0.f, 0.f, 0.f, 0.f);
      if (k < 65) w = *(const float4*)(p.Wh1 + (128 + k) * 128 + c4);
      uint2 pk;
      pk.x = h2pack(w.x, w.y);
      pk.y = h2pack(w.z, w.w);
      *(uint2*)(sm + ON_W1b + swb(k, c4)) = pk;
    }
    // W2: cols 0..63 = Wh2, cols 64..127 = 0
    for (int i = tid; i < 4096; i += 512) {
      int k  = i >> 5;
      int c4 = (i & 31) << 2;
      float4 w = make_float4(0.f, 0.f, 0.f, 0.f);
      if (c4 < 64) w = *(const float4*)(p.Wh2 + k * 64 + c4);
      uint2 pk;
      pk.x = h2pack(w.x, w.y);
      pk.y = h2pack(w.z, w.w);
      *(uint2*)(sm + ON_W2 + swb(k, c4)) = pk;
    }
    if (tid < 128) {
      ((float*)(sm + ON_BH1))[tid]  = p.bh1[tid];
      ((float*)(sm + ON_GH1))[tid]  = p.gh1[tid];
      ((float*)(sm + ON_BTH1))[tid] = p.bth1[tid];
    }
    if (tid < 64) ((float*)(sm + ON_BH2))[tid] = p.bh2[tid];
  }

  float* sRden = (float*)(sm + ON_RDEN);

  // den / nrm / A2 upper half (row tid)
  if (tid < 256) {
    int n = n0 + tid;
    float den = 1.f, nrm = 0.f;
    if (n < NNODES) {
      den = fmaxf(g_cnt[n], 1.f);
      float mvx = g_mv[2 * n] / den + 1e-8f;
      float mvy = g_mv[2 * n + 1] / den + 1e-8f;
      nrm = sqrtf(mvx * mvx + mvy * mvy);
    }
    sRden[tid] = 1.f / den;
    *(uint2*)(sm + ON_A2 + swb(tid, 64)) = make_uint2(h2pack(nrm, 0.f), 0u);
    uint2 z = make_uint2(0u, 0u);
#pragma unroll
    for (int gg = 1; gg < 16; ++gg)
      *(uint2*)(sm + ON_A2 + swb(tid, 64 + gg * 4)) = z;
  }
  __syncthreads();  // sRden ready (+ weights)

  // A1 fill: cols 0..63 = x, 64..127 = mh[0..63]/den
  for (int i = tid; i < 256 * 32; i += 512) {
    int row = i >> 5, grp = i & 31;
    int n = n0 + row;
    float4 w = make_float4(0.f, 0.f, 0.f, 0.f);
    if (n < NNODES) {
      if (grp < 16) {
        w = *(const float4*)(p.x + n * 64 + grp * 4);
      } else {
        w = *(const float4*)(g_mh + n * 128 + (grp - 16) * 4);
        float rd = sRden[row];
        w.x *= rd; w.y *= rd; w.z *= rd; w.w *= rd;
      }
    }
    uint2 pk;
    pk.x = h2pack(w.x, w.y);
    pk.y = h2pack(w.z, w.w);
    *(uint2*)(sm + ON_A1 + swb(row, grp * 4)) = pk;
  }
  // A2 main fill: cols 0..63 = mh[64..127]/den
  for (int i = tid; i < 256 * 16; i += 512) {
    int row = i >> 4, grp = i & 15;
    int n = n0 + row;
    float4 w = make_float4(0.f, 0.f, 0.f, 0.f);
    if (n < NNODES) {
      w = *(const float4*)(g_mh + n * 128 + 64 + grp * 4);
      float rd = sRden[row];
      w.x *= rd; w.y *= rd; w.z *= rd; w.w *= rd;
    }
    uint2 pk;
    pk.x = h2pack(w.x, w.y);
    pk.y = h2pack(w.z, w.w);
    *(uint2*)(sm + ON_A2 + swb(row, grp * 4)) = pk;
  }
  __syncthreads();

  const uint32_t smb = smem_u32(sm);
  const int g  = lane >> 2;
  const int q  = lane & 3;
  const int m0 = wid * 16;
  const int rA = m0 + g;
  const int rB = rA + 8;
  const float* cBH1 = (const float*)(sm + ON_BH1);
  const float* cGH1 = (const float*)(sm + ON_GH1);
  const float* cBT1 = (const float*)(sm + ON_BTH1);
  const float* cBH2 = (const float*)(sm + ON_BH2);

  float acc[16][4];
  // stage 1: hin @ Wh1 over both K-halves
  warp_gemm<false, true>(smb + ON_A1, smb + ON_W1a, 0, 0, m0, lane, acc);
  warp_gemm<false, false>(smb + ON_A2, smb + ON_W1b, 0, 0, m0, lane, acc);
  {
    float sa = 0.f, s2a = 0.f, sb = 0.f, s2b = 0.f;
#pragma unroll
    for (int f = 0; f < 16; ++f) {
#pragma unroll
      for (int t = 0; t < 2; ++t) {
        int c = 8 * f + 2 * q + t;
        float bb = cBH1[c];
        float za = acc[f][t] + bb;
        float zb = acc[f][2 + t] + bb;
        acc[f][t] = za;
        acc[f][2 + t] = zb;
        sa += za; s2a = fmaf(za, za, s2a);
        sb += zb; s2b = fmaf(zb, zb, s2b);
      }
    }
#pragma unroll
    for (int m = 1; m < 4; m <<= 1) {
      sa  += __shfl_xor_sync(0xffffffffu, sa, m);
      s2a += __shfl_xor_sync(0xffffffffu, s2a, m);
      sb  += __shfl_xor_sync(0xffffffffu, sb, m);
      s2b += __shfl_xor_sync(0xffffffffu, s2b, m);
    }
    float mua = sa * (1.f / 128.f);
    float ria = rsqrtf(s2a * (1.f / 128.f) - mua * mua + 1e-5f);
    float mub = sb * (1.f / 128.f);
    float rib = rsqrtf(s2b * (1.f / 128.f) - mub * mub + 1e-5f);
#pragma unroll
    for (int f = 0; f < 16; ++f) {
      int c0 = 8 * f + 2 * q;
      float ha0 = softplus_f((acc[f][0] - mua) * ria * cGH1[c0] + cBT1[c0]);
      float ha1 = softplus_f((acc[f][1] - mua) * ria * cGH1[c0 + 1] + cBT1[c0 + 1]);
      float hb0 = softplus_f((acc[f][2] - mub) * rib * cGH1[c0] + cBT1[c0]);
      float hb1 = softplus_f((acc[f][3] - mub) * rib * cGH1[c0 + 1] + cBT1[c0 + 1]);
      *(uint32_t*)(sm + ON_A1 + swb(rA, c0)) = h2pack(ha0, ha1);
      *(uint32_t*)(sm + ON_A1 + swb(rB, c0)) = h2pack(hb0, hb1);
    }
  }
  __syncwarp();
  // stage 2: H @ Wh2 (N=64 live in f 0..7) + residual
  warp_gemm<false, true>(smb + ON_A1, smb + ON_W2, 0, 0, m0, lane, acc);
  {
    int nA = n0 + rA, nB = n0 + rB;
#pragma unroll
    for (int f = 0; f < 8; ++f) {
      int c0 = 8 * f + 2 * q;
      float b0 = cBH2[c0], b1 = cBH2[c0 + 1];
      if (nA < NNODES) {
        float2 xv = *(const float2*)(p.x + nA * 64 + c0);
        float2 o;
        o.x = xv.x + acc[f][0] + b0;
        o.y = xv.y + acc[f][1] + b1;
        *(float2*)(p.out + nA * 64 + c0) = o;
      }
      if (nB < NNODES) {
        float2 xv = *(const float2*)(p.x + nB * 64 + c0);
        float2 o;
        o.x = xv.x + acc[f][2] + b0;
        o.y = xv.y + acc[f][3] + b1;
        *(float2*)(p.out + nB * 64 + c0) = o;
      }
    }
  }
}

// ------------------------------ launch -------------------------------------
extern "C" void kernel_launch(void* const* d_in, const int* in_sizes, int n_in,
                              void* d_out, int out_size) {
  EdgeParams ep;
  ep.x    = (const float*)d_in[0];
  ep.pos  = (const float*)d_in[1];
  ep.vel  = (const float*)d_in[2];
  ep.We1  = (const float*)d_in[3];
  ep.be1  = (const float*)d_in[4];
  ep.ge1  = (const float*)d_in[5];
  ep.bte1 = (const float*)d_in[6];
  ep.We2  = (const float*)d_in[7];
  ep.be2  = (const float*)d_in[8];
  ep.We3  = (const float*)d_in[9];
  ep.be3  = (const float*)d_in[10];
  ep.Wv1  = (const float*)d_in[11];
  ep.bv1  = (const float*)d_in[12];
  ep.gv1  = (const float*)d_in[13];
  ep.btv1 = (const float*)d_in[14];
  ep.Wv2  = (const float*)d_in[15];
  ep.bv2  = (const float*)d_in[16];
  ep.ei   = (const int*)d_in[23];

  NodeParams np;
  np.x    = ep.x;
  np.Wh1  = (const float*)d_in[17];
  np.bh1  = (const float*)d_in[18];
  np.gh1  = (const float*)d_in[19];
  np.bth1 = (const float*)d_in[20];
  np.Wh2  = (const float*)d_in[21];
  np.bh2  = (const float*)d_in[22];
  np.out  = (float*)d_out;

  cudaFuncSetAttribute(edge_kernel, cudaFuncAttributeMaxDynamicSharedMemorySize,
                       EDGE_SMEM);
  cudaFuncSetAttribute(node_kernel, cudaFuncAttributeMaxDynamicSharedMemorySize,
                       NODE_SMEM);

  zero_kernel<<<(NNODES * H + 255) / 256, 256>>>();
  edge_kernel<<<148, 512, EDGE_SMEM>>>(ep);
  node_kernel<<<NODE_CTAS, 512, NODE_SMEM>>>(np);
}